// round 14
// baseline (speedup 1.0000x reference)
#include <cuda_runtime.h>
#include <cuda_fp16.h>
#include <cstdint>
#include <math.h>

// ---------------- problem dims ----------------
#define TOK   4096
#define SEQL  2048
#define Hh    1024
#define Ee    2048
#define NHh   32
#define Nn    128
#define Qq    128
#define Kc    4
#define CONVD 2304
#define DIN   4384
#define FFd   4096
#define NCHUNK 32
#define EPS1  1e-6f
#define NEPS  1e-5f

// ---------------- scratch ----------------
__device__ __half g_hnorm [TOK * Hh];
__device__ float  g_zx    [TOK * DIN];
__device__ __half g_xbch  [TOK * CONVD];
__device__ float  g_dt    [TOK * NHh];
__device__ float  g_acs   [NCHUNK * NHh * Qq];
__device__ float  g_states[NCHUNK * NHh * 64 * Nn];
__device__ float  g_prefix[NCHUNK * NHh * 64 * Nn];
__device__ float  g_cb    [NCHUNK * Qq * Qq];
__device__ __half g_yh    [TOK * Ee];
__device__ __half g_y2    [TOK * Ee];
__device__ float  g_hid2  [TOK * Hh];
__device__ __half g_h2n   [TOK * Hh];
__device__ __half g_gateh [TOK * FFd];
__device__ __half g_gu    [TOK * FFd];
// fp16 weights
__device__ __half g_wh_in [DIN * Hh];
__device__ __half g_wh_out[Hh * Ee];
__device__ __half g_wh_g  [FFd * Hh];
__device__ __half g_wh_u  [FFd * Hh];
__device__ __half g_wh_d  [Hh * FFd];

// ---------------- helpers ----------------
__device__ __forceinline__ uint32_t smem_u32(const void* p) {
    return (uint32_t)__cvta_generic_to_shared(p);
}
__device__ __forceinline__ float silu_f(float x) { return x / (1.f + expf(-x)); }
__device__ __forceinline__ float block_sum_256(float v) {
    __shared__ float sh[8];
    __syncthreads();
    int lane = threadIdx.x & 31, wid = threadIdx.x >> 5;
#pragma unroll
    for (int o = 16; o > 0; o >>= 1) v += __shfl_down_sync(0xffffffffu, v, o);
    if (lane == 0) sh[wid] = v;
    __syncthreads();
    if (threadIdx.x == 0) {
        float s = 0.f;
#pragma unroll
        for (int i = 0; i < 8; i++) s += sh[i];
        sh[0] = s;
    }
    __syncthreads();
    return sh[0];
}
__device__ __forceinline__ void cp_async16(uint32_t dst, const void* src, int sz) {
    asm volatile("cp.async.cg.shared.global [%0], [%1], 16, %2;"
                 :: "r"(dst), "l"((unsigned long long)__cvta_generic_to_global(src)), "r"(sz)
                 : "memory");
}
__device__ __forceinline__ void ldsm_x4(uint32_t& r0, uint32_t& r1, uint32_t& r2, uint32_t& r3,
                                        uint32_t addr) {
    asm volatile("ldmatrix.sync.aligned.m8n8.x4.shared.b16 {%0,%1,%2,%3}, [%4];"
                 : "=r"(r0), "=r"(r1), "=r"(r2), "=r"(r3) : "r"(addr));
}
__device__ __forceinline__ uint2 f4_to_h4(float4 v) {
    __half2 lo = __floats2half2_rn(v.x, v.y);
    __half2 hi = __floats2half2_rn(v.z, v.w);
    return make_uint2(*(uint32_t*)&lo, *(uint32_t*)&hi);
}
__device__ __forceinline__ void mma_16816(float* a4, const uint32_t* fa, uint32_t b0, uint32_t b1) {
    asm volatile(
        "mma.sync.aligned.m16n8k16.row.col.f32.f16.f16.f32 "
        "{%0,%1,%2,%3}, {%4,%5,%6,%7}, {%8,%9}, {%0,%1,%2,%3};"
        : "+f"(a4[0]), "+f"(a4[1]), "+f"(a4[2]), "+f"(a4[3])
        : "r"(fa[0]), "r"(fa[1]), "r"(fa[2]), "r"(fa[3]), "r"(b0), "r"(b1));
}

// ---------------- fp16 mma.sync GEMM: C[M,N] = A[M,K] @ B[N,K]^T ----------------
// 128x64 CTA tile, BK=32, 4-stage cp.async + frag double-buffer, 3 CTAs/SM target.
// 8 warps 4(M)x2(N), warp tile 32x32.
// MODE: 0=f32 store, 1=f32+addsrc, 2=half silu(aux)*acc, 3=half store
#define GSTAGES 4
#define LDSTH 40
#define STAGE_HALVES (192 * LDSTH)                  // 128 A rows + 64 B rows
#define STAGE_BYTES  (STAGE_HALVES * 2)             // 15360
#define GEMM_DSMEM (GSTAGES * STAGE_BYTES)          // 61440

template<int MODE>
__global__ __launch_bounds__(256, 3) void mma_gemm(
    const __half* __restrict__ A, const __half* __restrict__ B,
    const void* __restrict__ aux, float* __restrict__ Cf, __half* __restrict__ Ch,
    int M, int N, int K, int col_base)
{
    extern __shared__ __half smh[];
    int tid = threadIdx.x;
    int lane = tid & 31, wid = tid >> 5;
    int g = lane >> 2, tg = lane & 3;
    int wm = (wid >> 1) << 5;        // 0,32,64,96
    int wn = (wid & 1) << 5;         // 0,32
    int row0 = blockIdx.y << 7, col0 = (blockIdx.x << 6) + col_base;
    int NC = K >> 5;
    uint32_t smbase = smem_u32(smh);

    uint32_t aoff[2], boff[2];
#pragma unroll
    for (int mt = 0; mt < 2; mt++)
        aoff[mt] = ((wm + (mt << 4) + (lane & 15)) * LDSTH + ((lane >> 4) << 3)) * 2;
#pragma unroll
    for (int ntp = 0; ntp < 2; ntp++)
        boff[ntp] = (128 * LDSTH + (wn + (ntp << 4) + (lane & 7) + (((lane >> 4) & 1) << 3)) * LDSTH
                     + (((lane >> 3) & 1) << 3)) * 2;

    float acc[2][4][4];
#pragma unroll
    for (int i = 0; i < 2; i++)
#pragma unroll
        for (int j = 0; j < 4; j++)
#pragma unroll
            for (int k = 0; k < 4; k++) acc[i][j][k] = 0.f;

    auto load_stage = [&](int s, int c) {
        __half* As = smh + s * STAGE_HALVES;
        __half* Bs = As + 128 * LDSTH;
        const __half* Ag = A + (size_t)row0 * K + (c << 5);
        const __half* Bg = B + (size_t)col0 * K + (c << 5);
#pragma unroll
        for (int it = 0; it < 3; it++) {
            int i = tid + (it << 8);
            if (i < 512) {
                int r = i >> 2, c8 = (i & 3) << 3;
                cp_async16(smem_u32(As + r * LDSTH + c8), Ag + (size_t)r * K + c8, 16);
            } else {
                int j = i - 512;
                int r = j >> 2, c8 = (j & 3) << 3;
                int sz = (col0 + r < N) ? 16 : 0;
                cp_async16(smem_u32(Bs + r * LDSTH + c8), Bg + (size_t)r * K + c8, sz);
            }
        }
    };

    uint32_t fa0[2][4], fb0[2][4], fa1[2][4], fb1[2][4];

    auto load_frags = [&](uint32_t (&fa)[2][4], uint32_t (&fb)[2][4], uint32_t stb, int ks) {
        uint32_t kb = stb + (ks << 5);
#pragma unroll
        for (int mt = 0; mt < 2; mt++)
            ldsm_x4(fa[mt][0], fa[mt][1], fa[mt][2], fa[mt][3], kb + aoff[mt]);
#pragma unroll
        for (int ntp = 0; ntp < 2; ntp++)
            ldsm_x4(fb[ntp][0], fb[ntp][1], fb[ntp][2], fb[ntp][3], kb + boff[ntp]);
    };
    auto do_mma = [&](uint32_t (&fa)[2][4], uint32_t (&fb)[2][4]) {
#pragma unroll
        for (int mt = 0; mt < 2; mt++)
#pragma unroll
            for (int nt = 0; nt < 4; nt++)
                mma_16816(acc[mt][nt], fa[mt],
                          fb[nt >> 1][((nt & 1) << 1)], fb[nt >> 1][((nt & 1) << 1) + 1]);
    };

#pragma unroll
    for (int s = 0; s < GSTAGES - 1; s++) {
        load_stage(s, s);
        asm volatile("cp.async.commit_group;" ::: "memory");
    }
    asm volatile("cp.async.wait_group %0;" :: "n"(GSTAGES - 2) : "memory");
    __syncthreads();
    load_frags(fa0, fb0, smbase, 0);

    for (int c = 0; c < NC; c++) {
        int nxt = c + GSTAGES - 1;
        if (nxt < NC) load_stage(nxt % GSTAGES, nxt);
        asm volatile("cp.async.commit_group;" ::: "memory");

        uint32_t stb = smbase + (c % GSTAGES) * STAGE_BYTES;
        load_frags(fa1, fb1, stb, 1);
        do_mma(fa0, fb0);

        if (c + 1 < NC) {
            asm volatile("cp.async.wait_group %0;" :: "n"(GSTAGES - 2) : "memory");
            __syncthreads();
            load_frags(fa0, fb0, smbase + ((c + 1) % GSTAGES) * STAGE_BYTES, 0);
        }
        do_mma(fa1, fb1);
    }

    // epilogue
#pragma unroll
    for (int mt = 0; mt < 2; mt++) {
        int r = row0 + wm + (mt << 4) + g;
#pragma unroll
        for (int nt = 0; nt < 4; nt++) {
            int cc = col0 + wn + (nt << 3) + (tg << 1);
            if (cc >= N) continue;
            float v0 = acc[mt][nt][0], v1 = acc[mt][nt][1];
            float v2 = acc[mt][nt][2], v3 = acc[mt][nt][3];
            if (MODE == 1) {
                const float* af = (const float*)aux;
                float2 s0 = *(const float2*)(af + (size_t)r * N + cc);
                float2 s1 = *(const float2*)(af + (size_t)(r + 8) * N + cc);
                v0 += s0.x; v1 += s0.y; v2 += s1.x; v3 += s1.y;
            }
            if (MODE == 2) {
                const __half* ah = (const __half*)aux;
                float2 gf0 = __half22float2(*(const __half2*)(ah + (size_t)r * N + cc));
                float2 gf1 = __half22float2(*(const __half2*)(ah + (size_t)(r + 8) * N + cc));
                *(__half2*)(Ch + (size_t)r * N + cc) =
                    __floats2half2_rn(silu_f(gf0.x) * v0, silu_f(gf0.y) * v1);
                *(__half2*)(Ch + (size_t)(r + 8) * N + cc) =
                    __floats2half2_rn(silu_f(gf1.x) * v2, silu_f(gf1.y) * v3);
            } else if (MODE == 3) {
                *(__half2*)(Ch + (size_t)r * N + cc) = __floats2half2_rn(v0, v1);
                *(__half2*)(Ch + (size_t)(r + 8) * N + cc) = __floats2half2_rn(v2, v3);
            } else if (MODE != 2) {
                *(float2*)(Cf + (size_t)r * N + cc) = make_float2(v0, v1);
                *(float2*)(Cf + (size_t)(r + 8) * N + cc) = make_float2(v2, v3);
            }
        }
    }
}

// ---------------- weight fp16 conversions ----------------
__global__ void round_h4_kernel(const float4* __restrict__ in, uint2* __restrict__ out, int n4) {
    int i = blockIdx.x * blockDim.x + threadIdx.x;
    if (i < n4) out[i] = f4_to_h4(in[i]);
}
__global__ void round4v_kernel(const float4* __restrict__ s0, uint2* __restrict__ d0, int n0,
                               const float4* __restrict__ s1, uint2* __restrict__ d1, int n1,
                               const float4* __restrict__ s2, uint2* __restrict__ d2, int n2,
                               const float4* __restrict__ s3, uint2* __restrict__ d3, int n3) {
    int i = blockIdx.x * blockDim.x + threadIdx.x;
    if (i < n0) { d0[i] = f4_to_h4(s0[i]); return; }
    i -= n0;
    if (i < n1) { d1[i] = f4_to_h4(s1[i]); return; }
    i -= n1;
    if (i < n2) { d2[i] = f4_to_h4(s2[i]); return; }
    i -= n2;
    if (i < n3) d3[i] = f4_to_h4(s3[i]);
}

// ---------------- rmsnorm (half output) ----------------
__global__ void rmsnorm_kernel(const float* __restrict__ x, const float* __restrict__ w,
                               __half* __restrict__ out, int cols, float eps) {
    int row = blockIdx.x;
    const float* xr = x + (size_t)row * cols;
    __half* orow = out + (size_t)row * cols;
    int per = cols >> 8;
    float xv[8];
    float ss = 0.f;
    for (int i = 0; i < per; i++) {
        float v = xr[threadIdx.x + (i << 8)];
        xv[i] = v; ss += v * v;
    }
    float tot = block_sum_256(ss);
    float scale = rsqrtf(tot / (float)cols + eps);
    for (int i = 0; i < per; i++) {
        int c = threadIdx.x + (i << 8);
        orow[c] = __float2half(xv[i] * scale * w[c]);
    }
}

// gated rmsnorm
__global__ void gated_rmsnorm_kernel(const __half* __restrict__ y, const float* __restrict__ zx,
                                     const float* __restrict__ w, __half* __restrict__ out) {
    int row = blockIdx.x;
    const __half* yr = y + (size_t)row * Ee;
    const float* zr = zx + (size_t)row * DIN;
    __half* orow = out + (size_t)row * Ee;
    float g[8];
    float ss = 0.f;
#pragma unroll
    for (int i = 0; i < 8; i++) {
        int c = threadIdx.x + (i << 8);
        float v = __half2float(yr[c]) * silu_f(zr[c]);
        g[i] = v; ss += v * v;
    }
    float tot = block_sum_256(ss);
    float scale = rsqrtf(tot / (float)Ee + NEPS);
#pragma unroll
    for (int i = 0; i < 8; i++) {
        int c = threadIdx.x + (i << 8);
        orow[c] = __float2half(g[i] * scale * w[c]);
    }
}

// ---------------- conv + silu (half output) ----------------
__global__ void conv_silu_kernel(const float* __restrict__ zx,
                                 const float* __restrict__ wc,
                                 const float* __restrict__ bcv,
                                 __half* __restrict__ xbc) {
    int idx = blockIdx.x * blockDim.x + threadIdx.x;
    if (idx >= TOK * CONVD) return;
    int t = idx / CONVD, c = idx - t * CONVD;
    int pos = t & (SEQL - 1);
    float s = bcv[c];
#pragma unroll
    for (int k = 0; k < Kc; k++) {
        int sp = pos - (Kc - 1) + k;
        if (sp >= 0)
            s += zx[(size_t)(t - (Kc - 1) + k) * DIN + Ee + c] * wc[c * Kc + k];
    }
    xbc[idx] = __float2half(silu_f(s));
}

// ---------------- dt softplus + per-chunk cumsum ----------------
__global__ void dtdacs_kernel(const float* __restrict__ zx, const float* __restrict__ dtb,
                              const float* __restrict__ alog,
                              float* __restrict__ dt, float* __restrict__ acs) {
    int bc = blockIdx.x, h = blockIdx.y;
    int tb = ((bc >> 4) << 11) + ((bc & 15) << 7);
    int q = threadIdx.x;
    int t = tb + q;
    float x = zx[(size_t)t * DIN + (Ee + CONVD) + h] + dtb[h];
    float d = (x > 20.f) ? x : log1pf(expf(x));
    dt[t * NHh + h] = d;
    float a = -expf(alog[h]);
    float v = d * a;
    int lane = q & 31;
#pragma unroll
    for (int o = 1; o < 32; o <<= 1) {
        float n = __shfl_up_sync(0xffffffffu, v, o);
        if (lane >= o) v += n;
    }
    __shared__ float ws[4];
    int wid = q >> 5;
    if (lane == 31) ws[wid] = v;
    __syncthreads();
    float add = 0.f;
    for (int w = 0; w < wid; w++) add += ws[w];
    acs[(bc * NHh + h) * Qq + q] = v + add;
}

// ================= SSD on tensor cores =================
#define SST 136

#define CS_DSMEM (192 * SST * 2 + 512)
__global__ __launch_bounds__(128) void chunk_states_mma(
    const __half* __restrict__ xbc, const float* __restrict__ dt,
    const float* __restrict__ acs, float* __restrict__ states) {
    extern __shared__ __half smh[];
    __half* Ah = smh;
    __half* Bh = smh + 64 * SST;
    float* wsh = (float*)(smh + 192 * SST);

    int bc = blockIdx.x, h = blockIdx.y;
    int tb = ((bc >> 4) << 11) + ((bc & 15) << 7);
    int tid = threadIdx.x, lane = tid & 31, wid = tid >> 5;
    int g = lane >> 2, tg = lane & 3;

    const float* ac = acs + (bc * NHh + h) * Qq;
    if (tid < 128) {
        float last = ac[127];
        wsh[tid] = __expf(last - ac[tid]) * dt[(tb + tid) * NHh + h];
    }
    __syncthreads();

    for (int i = tid; i < 64 * 128; i += 128) {
        int q = i >> 6, p = i & 63;
        float v = __half2float(xbc[(size_t)(tb + q) * CONVD + h * 64 + p]) * wsh[q];
        Ah[p * SST + q] = __float2half(v);
    }
    for (int i = tid; i < 128 * 128; i += 128) {
        int q = i >> 7, n = i & 127;
        Bh[n * SST + q] = xbc[(size_t)(tb + q) * CONVD + 2048 + n];
    }
    __syncthreads();

    int wm = (wid >> 1) << 5;
    int wn = (wid & 1) << 6;
    uint32_t abase = smem_u32(Ah), bbase = smem_u32(Bh);
    uint32_t aoff[2], boff[4];
#pragma unroll
    for (int mt = 0; mt < 2; mt++)
        aoff[mt] = abase + ((wm + (mt << 4) + (lane & 15)) * SST + ((lane >> 4) << 3)) * 2;
#pragma unroll
    for (int ntp = 0; ntp < 4; ntp++)
        boff[ntp] = bbase + ((wn + (ntp << 4) + (lane & 7) + (((lane >> 4) & 1) << 3)) * SST
                             + (((lane >> 3) & 1) << 3)) * 2;

    float acc[2][8][4] = {};
#pragma unroll
    for (int ks = 0; ks < 8; ks++) {
        uint32_t kb = ks << 5;
        uint32_t fa[2][4], fb[4][4];
#pragma unroll
        for (int mt = 0; mt < 2; mt++)
            ldsm_x4(fa[mt][0], fa[mt][1], fa[mt][2], fa[mt][3], aoff[mt] + kb);
#pragma unroll
        for (int ntp = 0; ntp < 4; ntp++)
            ldsm_x4(fb[ntp][0], fb[ntp][1], fb[ntp][2], fb[ntp][3], boff[ntp] + kb);
#pragma unroll
        for (int mt = 0; mt < 2; mt++)
#pragma unroll
            for (int nt = 0; nt < 8; nt++)
                mma_16816(acc[mt][nt], fa[mt],
                          fb[nt >> 1][((nt & 1) << 1)], fb[nt >> 1][((nt & 1) << 1) + 1]);
    }

    float* sp = states + (size_t)(bc * NHh + h) * 8192;
#pragma unroll
    for (int mt = 0; mt < 2; mt++) {
        int p = wm + (mt << 4) + g;
#pragma unroll
        for (int nt = 0; nt < 8; nt++) {
            int n = wn + (nt << 3) + (tg << 1);
            *(float2*)(sp + p * 128 + n) = make_float2(acc[mt][nt][0], acc[mt][nt][1]);
            *(float2*)(sp + (p + 8) * 128 + n) = make_float2(acc[mt][nt][2], acc[mt][nt][3]);
        }
    }
}

#define Y_DSMEM (192 * SST * 2 + 3 * 128 * 4)
__global__ __launch_bounds__(128) void y_mma_kernel(
    const __half* __restrict__ xbc, const float* __restrict__ dt,
    const float* __restrict__ acs, const float* __restrict__ prefix,
    const float* __restrict__ cb, const float* __restrict__ Dw,
    __half* __restrict__ y) {
    extern __shared__ __half smh[];
    __half* Ah = smh;
    __half* Bh = smh + 128 * SST;
    float* acs_s = (float*)(smh + 192 * SST);
    float* dts   = acs_s + 128;
    float* eqs   = dts + 128;

    int bc = blockIdx.x, h = blockIdx.y;
    int tb = ((bc >> 4) << 11) + ((bc & 15) << 7);
    int tid = threadIdx.x, lane = tid & 31, wid = tid >> 5;
    int g = lane >> 2, tg = lane & 3;

    if (tid < 128) {
        float a = acs[(bc * NHh + h) * Qq + tid];
        acs_s[tid] = a;
        eqs[tid] = __expf(a);
        dts[tid] = dt[(tb + tid) * NHh + h];
    }
    __syncthreads();

    const float* cbb = cb + (size_t)bc * 16384;
    for (int i = tid; i < 128 * 128; i += 128) {
        int q = i >> 7, s = i & 127;
        float v = (s <= q) ? cbb[q * 128 + s] * __expf(acs_s[q] - acs_s[s]) : 0.f;
        Ah[q * SST + s] = __float2half(v);
    }
    for (int i = tid; i < 64 * 128; i += 128) {
        int s = i >> 6, p = i & 63;
        float xv = __half2float(xbc[(size_t)(tb + s) * CONVD + h * 64 + p]);
        Bh[p * SST + s] = __float2half(xv * dts[s]);
    }
    __syncthreads();

    int wm = wid << 5;
    uint32_t abase = smem_u32(Ah), bbase = smem_u32(Bh);
    uint32_t aoff[2], boff[4];
#pragma unroll
    for (int mt = 0; mt < 2; mt++)
        aoff[mt] = abase + ((wm + (mt << 4) + (lane & 15)) * SST + ((lane >> 4) << 3)) * 2;
#pragma unroll
    for (int ntp = 0; ntp < 4; ntp++)
        boff[ntp] = bbase + (((ntp << 4) + (lane & 7) + (((lane >> 4) & 1) << 3)) * SST
                             + (((lane >> 3) & 1) << 3)) * 2;

    float acc[2][8][4] = {};
    auto run_phase = [&]() {
#pragma unroll
        for (int ks = 0; ks < 8; ks++) {
            uint32_t kb = ks << 5;
            uint32_t fa[2][4], fb[4][4];
#pragma unroll
            for (int mt = 0; mt < 2; mt++)
                ldsm_x4(fa[mt][0], fa[mt][1], fa[mt][2], fa[mt][3], aoff[mt] + kb);
#pragma unroll
            for (int ntp = 0; ntp < 4; ntp++)
                ldsm_x4(fb[ntp][0], fb[ntp][1], fb[ntp][2], fb[ntp][3], boff[ntp] + kb);
#pragma unroll
            for (int mt = 0; mt < 2; mt++)
#pragma unroll
                for (int nt = 0; nt < 8; nt++)
                    mma_16816(acc[mt][nt], fa[mt],
                              fb[nt >> 1][((nt & 1) << 1)], fb[nt >> 1][((nt & 1) << 1) + 1]);
        }
    };
    run_phase();
    __syncthreads();

    for (int i = tid; i < 128 * 128; i += 128) {
        int q = i >> 7, n = i & 127;
        float cv = __half2float(xbc[(size_t)(tb + q) * CONVD + 2176 + n]);
        Ah[q * SST + n] = __float2half(cv * eqs[q]);
    }
    const float* pref = prefix + (size_t)(bc * NHh + h) * 8192;
    for (int i = tid; i < 64 * 128; i += 128) {
        int p = i >> 7, n = i & 127;
        Bh[p * SST + n] = __float2half(pref[p * 128 + n]);
    }
    __syncthreads();
    run_phase();

    float Dh = Dw[h];
#pragma unroll
    for (int mt = 0; mt < 2; mt++) {
        int q = wm + (mt << 4) + g;
#pragma unroll
        for (int nt = 0; nt < 8; nt++) {
            int p = (nt << 3) + (tg << 1);
            {
                int t = tb + q;
                float2 xv = __half22float2(*(const __half2*)(xbc + (size_t)t * CONVD + h * 64 + p));
                *(__half2*)(y + (size_t)t * Ee + h * 64 + p) =
                    __floats2half2_rn(acc[mt][nt][0] + Dh * xv.x, acc[mt][nt][1] + Dh * xv.y);
            }
            {
                int t = tb + q + 8;
                float2 xv = __half22float2(*(const __half2*)(xbc + (size_t)t * CONVD + h * 64 + p));
                *(__half2*)(y + (size_t)t * Ee + h * 64 + p) =
                    __floats2half2_rn(acc[mt][nt][2] + Dh * xv.x, acc[mt][nt][3] + Dh * xv.y);
            }
        }
    }
}

// ---------------- inter-chunk recurrence ----------------
__global__ void chunk_scan_kernel(const float* __restrict__ states,
                                  const float* __restrict__ acs,
                                  float* __restrict__ prefix) {
    int b = blockIdx.x, h = blockIdx.y, tid = threadIdx.x;
    float run[32];
#pragma unroll
    for (int i = 0; i < 32; i++) run[i] = 0.f;
    for (int ch = 0; ch < 16; ch++) {
        int bc = b * 16 + ch;
        size_t base = (size_t)(bc * NHh + h) * 8192;
        float al = expf(acs[(bc * NHh + h) * Qq + 127]);
#pragma unroll
        for (int i = 0; i < 32; i++) {
            int e = (i << 8) + tid;
            prefix[base + e] = run[i];
            run[i] = run[i] * al + states[base + e];
        }
    }
}

// ---------------- CB (split over q; half input) ----------------
__global__ __launch_bounds__(256) void cb_kernel(const __half* __restrict__ xbc,
                                                 float* __restrict__ cbout) {
    int bc = blockIdx.x;
    int q0 = blockIdx.y << 6;
    int tb = ((bc >> 4) << 11) + ((bc & 15) << 7);
    __shared__ float Ct[64][33];
    __shared__ float Bt[128][33];
    int tid = threadIdx.x;
    int tq = tid >> 4, ts = tid & 15;
    float acc[4][8] = {};
    for (int nt = 0; nt < 128; nt += 32) {
        for (int i = tid; i < 2048; i += 256) {
            int r = i >> 5, nn = i & 31;
            Ct[r][nn] = __half2float(xbc[(size_t)(tb + q0 + r) * CONVD + 2176 + nt + nn]);
        }
        for (int i = tid; i < 4096; i += 256) {
            int r = i >> 5, nn = i & 31;
            Bt[r][nn] = __half2float(xbc[(size_t)(tb + r) * CONVD + 2048 + nt + nn]);
        }
        __syncthreads();
        for (int nn = 0; nn < 32; nn++) {
            float ca[4], bb[8];
#pragma unroll
            for (int i = 0; i < 4; i++) ca[i] = Ct[tq * 4 + i][nn];
#pragma unroll
            for (int j = 0; j < 8; j++) bb[j] = Bt[ts * 8 + j][nn];
#pragma unroll
            for (int i = 0; i < 4; i++)
#pragma unroll
                for (int j = 0; j < 8; j++) acc[i][j] += ca[i] * bb[j];
        }
        __syncthreads();
    }
    float* o = cbout + (size_t)bc * 16384;
#pragma unroll
    for (int i = 0; i < 4; i++)
#pragma unroll
        for (int j = 0; j < 8; j++)
            o[(q0 + tq * 4 + i) * 128 + ts * 8 + j] = acc[i][j];
}

// ---------------- host launcher ----------------
extern "C" void kernel_launch(void* const* d_in, const int* in_sizes, int n_in,
                              void* d_out, int out_size) {
    const float* hid   = (const float*)d_in[0];
    const float* wln1  = (const float*)d_in[1];
    const float* win   = (const float*)d_in[2];
    const float* wconv = (const float*)d_in[3];
    const float* bcv   = (const float*)d_in[4];
    const float* dtb   = (const float*)d_in[5];
    const float* alog  = (const float*)d_in[6];
    const float* Dw    = (const float*)d_in[7];
    const float* wmn   = (const float*)d_in[8];
    const float* wout  = (const float*)d_in[9];
    const float* wln2  = (const float*)d_in[10];
    const float* wg    = (const float*)d_in[11];
    const float* wu    = (const float*)d_in[12];
    const float* wd    = (const float*)d_in[13];
    float* out = (float*)d_out;

    __half *hnorm, *xbch, *yh, *y2, *h2n, *ggh, *gu, *wh_in, *wh_out, *wh_g, *wh_u, *wh_d;
    float *zx, *dt, *acs, *states, *prefix, *cbp, *hid2;
    cudaGetSymbolAddress((void**)&hnorm,  g_hnorm);
    cudaGetSymbolAddress((void**)&zx,     g_zx);
    cudaGetSymbolAddress((void**)&xbch,   g_xbch);
    cudaGetSymbolAddress((void**)&dt,     g_dt);
    cudaGetSymbolAddress((void**)&acs,    g_acs);
    cudaGetSymbolAddress((void**)&states, g_states);
    cudaGetSymbolAddress((void**)&prefix, g_prefix);
    cudaGetSymbolAddress((void**)&cbp,    g_cb);
    cudaGetSymbolAddress((void**)&yh,     g_yh);
    cudaGetSymbolAddress((void**)&y2,     g_y2);
    cudaGetSymbolAddress((void**)&hid2,   g_hid2);
    cudaGetSymbolAddress((void**)&h2n,    g_h2n);
    cudaGetSymbolAddress((void**)&ggh,    g_gateh);
    cudaGetSymbolAddress((void**)&gu,     g_gu);
    cudaGetSymbolAddress((void**)&wh_in,  g_wh_in);
    cudaGetSymbolAddress((void**)&wh_out, g_wh_out);
    cudaGetSymbolAddress((void**)&wh_g,   g_wh_g);
    cudaGetSymbolAddress((void**)&wh_u,   g_wh_u);
    cudaGetSymbolAddress((void**)&wh_d,   g_wh_d);

    cudaFuncSetAttribute(mma_gemm<0>, cudaFuncAttributeMaxDynamicSharedMemorySize, GEMM_DSMEM);
    cudaFuncSetAttribute(mma_gemm<1>, cudaFuncAttributeMaxDynamicSharedMemorySize, GEMM_DSMEM);
    cudaFuncSetAttribute(mma_gemm<2>, cudaFuncAttributeMaxDynamicSharedMemorySize, GEMM_DSMEM);
    cudaFuncSetAttribute(mma_gemm<3>, cudaFuncAttributeMaxDynamicSharedMemorySize, GEMM_DSMEM);
    cudaFuncSetAttribute(chunk_states_mma, cudaFuncAttributeMaxDynamicSharedMemorySize, CS_DSMEM);
    cudaFuncSetAttribute(y_mma_kernel, cudaFuncAttributeMaxDynamicSharedMemorySize, Y_DSMEM);

    // 0) in-proj weights -> fp16
    round_h4_kernel<<<(DIN * Hh / 4 + 255) / 256, 256>>>((const float4*)win, (uint2*)wh_in, DIN * Hh / 4);
    // 1) pre-norm
    rmsnorm_kernel<<<TOK, 256>>>(hid, wln1, hnorm, Hh, EPS1);
    // 2) in-projection (69 x 32 grid, N=4384 edge guarded)
    mma_gemm<0><<<dim3((DIN + 63) / 64, TOK / 128), 256, GEMM_DSMEM>>>(hnorm, wh_in, nullptr, zx, nullptr, TOK, DIN, Hh, 0);
    // 3) conv + silu
    conv_silu_kernel<<<(TOK * CONVD + 255) / 256, 256>>>(zx, wconv, bcv, xbch);
    // 4) dt + cumsum
    dtdacs_kernel<<<dim3(NCHUNK, NHh), 128>>>(zx, dtb, alog, dt, acs);
    // 5) chunk states (mma)
    chunk_states_mma<<<dim3(NCHUNK, NHh), 128, CS_DSMEM>>>(xbch, dt, acs, states);
    // 6) scan
    chunk_scan_kernel<<<dim3(2, NHh), 256>>>(states, acs, prefix);
    // 7) CB
    cb_kernel<<<dim3(NCHUNK, 2), 256>>>(xbch, cbp);
    // 8) Y (mma)
    y_mma_kernel<<<dim3(NCHUNK, NHh), 128, Y_DSMEM>>>(xbch, dt, acs, prefix, cbp, Dw, yh);
    // 9) remaining weights -> fp16
    {
        int ntot = (Hh * Ee + FFd * Hh + FFd * Hh + Hh * FFd) / 4;
        round4v_kernel<<<(ntot + 255) / 256, 256>>>(
            (const float4*)wout, (uint2*)wh_out, Hh * Ee / 4,
            (const float4*)wg,   (uint2*)wh_g,   FFd * Hh / 4,
            (const float4*)wu,   (uint2*)wh_u,   FFd * Hh / 4,
            (const float4*)wd,   (uint2*)wh_d,   Hh * FFd / 4);
    }
    // 10) gated norm
    gated_rmsnorm_kernel<<<TOK, 256>>>(yh, zx, wmn, y2);
    // 11) out-proj + residual
    mma_gemm<1><<<dim3(Hh / 64, TOK / 128), 256, GEMM_DSMEM>>>(y2, wh_out, hid, hid2, nullptr, TOK, Hh, Ee, 0);
    // 12) norm 2
    rmsnorm_kernel<<<TOK, 256>>>(hid2, wln2, h2n, Hh, EPS1);
    // 13) gate projection (half out)
    mma_gemm<3><<<dim3(FFd / 64, TOK / 128), 256, GEMM_DSMEM>>>(h2n, wh_g, nullptr, nullptr, ggh, TOK, FFd, Hh, 0);
    // 14) up projection + fused silu(gate)*up
    mma_gemm<2><<<dim3(FFd / 64, TOK / 128), 256, GEMM_DSMEM>>>(h2n, wh_u, ggh, nullptr, gu, TOK, FFd, Hh, 0);
    // 15) down + residual -> output
    mma_gemm<1><<<dim3(Hh / 64, TOK / 128), 256, GEMM_DSMEM>>>(gu, wh_d, hid2, out, nullptr, TOK, Hh, FFd, 0);
}

// round 15
// speedup vs baseline: 1.1807x; 1.1807x over previous
#include <cuda_runtime.h>
#include <cuda_fp16.h>
#include <cstdint>
#include <math.h>

// ---------------- problem dims ----------------
#define TOK   4096
#define SEQL  2048
#define Hh    1024
#define Ee    2048
#define NHh   32
#define Nn    128
#define Qq    128
#define Kc    4
#define CONVD 2304
#define DIN   4384
#define FFd   4096
#define NCHUNK 32
#define EPS1  1e-6f
#define NEPS  1e-5f

// ---------------- scratch ----------------
__device__ __half g_hnorm [TOK * Hh];
__device__ float  g_zx    [TOK * DIN];
__device__ __half g_xbch  [TOK * CONVD];
__device__ float  g_dt    [TOK * NHh];
__device__ float  g_acs   [NCHUNK * NHh * Qq];
__device__ float  g_states[NCHUNK * NHh * 64 * Nn];
__device__ float  g_prefix[NCHUNK * NHh * 64 * Nn];
__device__ float  g_cb    [NCHUNK * Qq * Qq];
__device__ __half g_yh    [TOK * Ee];
__device__ __half g_y2    [TOK * Ee];
__device__ float  g_hid2  [TOK * Hh];
__device__ __half g_h2n   [TOK * Hh];
__device__ __half g_gateh [TOK * FFd];
__device__ __half g_gu    [TOK * FFd];
// fp16 weights
__device__ __half g_wh_in [DIN * Hh];
__device__ __half g_wh_out[Hh * Ee];
__device__ __half g_wh_g  [FFd * Hh];
__device__ __half g_wh_u  [FFd * Hh];
__device__ __half g_wh_d  [Hh * FFd];

// ---------------- helpers ----------------
__device__ __forceinline__ uint32_t smem_u32(const void* p) {
    return (uint32_t)__cvta_generic_to_shared(p);
}
__device__ __forceinline__ float silu_f(float x) { return x / (1.f + expf(-x)); }
__device__ __forceinline__ float block_sum_256(float v) {
    __shared__ float sh[8];
    __syncthreads();
    int lane = threadIdx.x & 31, wid = threadIdx.x >> 5;
#pragma unroll
    for (int o = 16; o > 0; o >>= 1) v += __shfl_down_sync(0xffffffffu, v, o);
    if (lane == 0) sh[wid] = v;
    __syncthreads();
    if (threadIdx.x == 0) {
        float s = 0.f;
#pragma unroll
        for (int i = 0; i < 8; i++) s += sh[i];
        sh[0] = s;
    }
    __syncthreads();
    return sh[0];
}
__device__ __forceinline__ void cp_async16(uint32_t dst, const void* src, int sz) {
    asm volatile("cp.async.cg.shared.global [%0], [%1], 16, %2;"
                 :: "r"(dst), "l"((unsigned long long)__cvta_generic_to_global(src)), "r"(sz)
                 : "memory");
}
__device__ __forceinline__ void ldsm_x4(uint32_t& r0, uint32_t& r1, uint32_t& r2, uint32_t& r3,
                                        uint32_t addr) {
    asm volatile("ldmatrix.sync.aligned.m8n8.x4.shared.b16 {%0,%1,%2,%3}, [%4];"
                 : "=r"(r0), "=r"(r1), "=r"(r2), "=r"(r3) : "r"(addr));
}
__device__ __forceinline__ uint2 f4_to_h4(float4 v) {
    __half2 lo = __floats2half2_rn(v.x, v.y);
    __half2 hi = __floats2half2_rn(v.z, v.w);
    return make_uint2(*(uint32_t*)&lo, *(uint32_t*)&hi);
}
__device__ __forceinline__ void mma_16816(float* a4, const uint32_t* fa, uint32_t b0, uint32_t b1) {
    asm volatile(
        "mma.sync.aligned.m16n8k16.row.col.f32.f16.f16.f32 "
        "{%0,%1,%2,%3}, {%4,%5,%6,%7}, {%8,%9}, {%0,%1,%2,%3};"
        : "+f"(a4[0]), "+f"(a4[1]), "+f"(a4[2]), "+f"(a4[3])
        : "r"(fa[0]), "r"(fa[1]), "r"(fa[2]), "r"(fa[3]), "r"(b0), "r"(b1));
}

// ---------------- fp16 mma.sync GEMM (round-13 best config) ----------------
// 128x128 CTA tile, BK=32, 5-stage cp.async + frag double-buffer, 2 CTAs/SM.
#define GSTAGES 5
#define LDSTH 40
#define STAGE_HALVES (256 * LDSTH)
#define STAGE_BYTES  (STAGE_HALVES * 2)
#define GEMM_DSMEM (GSTAGES * STAGE_BYTES)

template<int MODE>
__global__ __launch_bounds__(256, 2) void mma_gemm(
    const __half* __restrict__ A, const __half* __restrict__ B,
    const void* __restrict__ aux, float* __restrict__ Cf, __half* __restrict__ Ch,
    int M, int N, int K, int col_base)
{
    extern __shared__ __half smh[];
    int tid = threadIdx.x;
    int lane = tid & 31, wid = tid >> 5;
    int g = lane >> 2, tg = lane & 3;
    int wm = (wid >> 1) << 5;
    int wn = (wid & 1) << 6;
    int row0 = blockIdx.y << 7, col0 = (blockIdx.x << 7) + col_base;
    int NC = K >> 5;
    uint32_t smbase = smem_u32(smh);

    uint32_t aoff[2], boff[4];
#pragma unroll
    for (int mt = 0; mt < 2; mt++)
        aoff[mt] = ((wm + (mt << 4) + (lane & 15)) * LDSTH + ((lane >> 4) << 3)) * 2;
#pragma unroll
    for (int ntp = 0; ntp < 4; ntp++)
        boff[ntp] = (128 * LDSTH + (wn + (ntp << 4) + (lane & 7) + (((lane >> 4) & 1) << 3)) * LDSTH
                     + (((lane >> 3) & 1) << 3)) * 2;

    float acc[2][8][4];
#pragma unroll
    for (int i = 0; i < 2; i++)
#pragma unroll
        for (int j = 0; j < 8; j++)
#pragma unroll
            for (int k = 0; k < 4; k++) acc[i][j][k] = 0.f;

    auto load_stage = [&](int s, int c) {
        __half* As = smh + s * STAGE_HALVES;
        __half* Bs = As + 128 * LDSTH;
        const __half* Ag = A + (size_t)row0 * K + (c << 5);
        const __half* Bg = B + (size_t)col0 * K + (c << 5);
#pragma unroll
        for (int it = 0; it < 4; it++) {
            int i = tid + (it << 8);
            if (i < 512) {
                int r = i >> 2, c8 = (i & 3) << 3;
                cp_async16(smem_u32(As + r * LDSTH + c8), Ag + (size_t)r * K + c8, 16);
            } else {
                int j = i - 512;
                int r = j >> 2, c8 = (j & 3) << 3;
                int sz = (col0 + r < N) ? 16 : 0;
                cp_async16(smem_u32(Bs + r * LDSTH + c8), Bg + (size_t)r * K + c8, sz);
            }
        }
    };

    uint32_t fa0[2][4], fb0[4][4], fa1[2][4], fb1[4][4];

    auto load_frags = [&](uint32_t (&fa)[2][4], uint32_t (&fb)[4][4], uint32_t stb, int ks) {
        uint32_t kb = stb + (ks << 5);
#pragma unroll
        for (int mt = 0; mt < 2; mt++)
            ldsm_x4(fa[mt][0], fa[mt][1], fa[mt][2], fa[mt][3], kb + aoff[mt]);
#pragma unroll
        for (int ntp = 0; ntp < 4; ntp++)
            ldsm_x4(fb[ntp][0], fb[ntp][1], fb[ntp][2], fb[ntp][3], kb + boff[ntp]);
    };
    auto do_mma = [&](uint32_t (&fa)[2][4], uint32_t (&fb)[4][4]) {
#pragma unroll
        for (int mt = 0; mt < 2; mt++)
#pragma unroll
            for (int nt = 0; nt < 8; nt++)
                mma_16816(acc[mt][nt], fa[mt],
                          fb[nt >> 1][((nt & 1) << 1)], fb[nt >> 1][((nt & 1) << 1) + 1]);
    };

#pragma unroll
    for (int s = 0; s < GSTAGES - 1; s++) {
        load_stage(s, s);
        asm volatile("cp.async.commit_group;" ::: "memory");
    }
    asm volatile("cp.async.wait_group %0;" :: "n"(GSTAGES - 2) : "memory");
    __syncthreads();
    load_frags(fa0, fb0, smbase, 0);

    for (int c = 0; c < NC; c++) {
        int nxt = c + GSTAGES - 1;
        if (nxt < NC) load_stage(nxt % GSTAGES, nxt);
        asm volatile("cp.async.commit_group;" ::: "memory");

        uint32_t stb = smbase + (c % GSTAGES) * STAGE_BYTES;
        load_frags(fa1, fb1, stb, 1);
        do_mma(fa0, fb0);

        if (c + 1 < NC) {
            asm volatile("cp.async.wait_group %0;" :: "n"(GSTAGES - 2) : "memory");
            __syncthreads();
            load_frags(fa0, fb0, smbase + ((c + 1) % GSTAGES) * STAGE_BYTES, 0);
        }
        do_mma(fa1, fb1);
    }

    // epilogue
#pragma unroll
    for (int mt = 0; mt < 2; mt++) {
        int r = row0 + wm + (mt << 4) + g;
#pragma unroll
        for (int nt = 0; nt < 8; nt++) {
            int cc = col0 + wn + (nt << 3) + (tg << 1);
            if (cc >= N) continue;
            float v0 = acc[mt][nt][0], v1 = acc[mt][nt][1];
            float v2 = acc[mt][nt][2], v3 = acc[mt][nt][3];
            if (MODE == 1) {
                const float* af = (const float*)aux;
                float2 s0 = *(const float2*)(af + (size_t)r * N + cc);
                float2 s1 = *(const float2*)(af + (size_t)(r + 8) * N + cc);
                v0 += s0.x; v1 += s0.y; v2 += s1.x; v3 += s1.y;
            }
            if (MODE == 2) {
                const __half* ah = (const __half*)aux;
                float2 gf0 = __half22float2(*(const __half2*)(ah + (size_t)r * N + cc));
                float2 gf1 = __half22float2(*(const __half2*)(ah + (size_t)(r + 8) * N + cc));
                *(__half2*)(Ch + (size_t)r * N + cc) =
                    __floats2half2_rn(silu_f(gf0.x) * v0, silu_f(gf0.y) * v1);
                *(__half2*)(Ch + (size_t)(r + 8) * N + cc) =
                    __floats2half2_rn(silu_f(gf1.x) * v2, silu_f(gf1.y) * v3);
            } else if (MODE == 3) {
                *(__half2*)(Ch + (size_t)r * N + cc) = __floats2half2_rn(v0, v1);
                *(__half2*)(Ch + (size_t)(r + 8) * N + cc) = __floats2half2_rn(v2, v3);
            } else if (MODE != 2) {
                *(float2*)(Cf + (size_t)r * N + cc) = make_float2(v0, v1);
                *(float2*)(Cf + (size_t)(r + 8) * N + cc) = make_float2(v2, v3);
            }
        }
    }
}

// ---------------- weight fp16 conversions ----------------
__global__ void round_h4_kernel(const float4* __restrict__ in, uint2* __restrict__ out, int n4) {
    int i = blockIdx.x * blockDim.x + threadIdx.x;
    if (i < n4) out[i] = f4_to_h4(in[i]);
}
__global__ void round4v_kernel(const float4* __restrict__ s0, uint2* __restrict__ d0, int n0,
                               const float4* __restrict__ s1, uint2* __restrict__ d1, int n1,
                               const float4* __restrict__ s2, uint2* __restrict__ d2, int n2,
                               const float4* __restrict__ s3, uint2* __restrict__ d3, int n3) {
    int i = blockIdx.x * blockDim.x + threadIdx.x;
    if (i < n0) { d0[i] = f4_to_h4(s0[i]); return; }
    i -= n0;
    if (i < n1) { d1[i] = f4_to_h4(s1[i]); return; }
    i -= n1;
    if (i < n2) { d2[i] = f4_to_h4(s2[i]); return; }
    i -= n2;
    if (i < n3) d3[i] = f4_to_h4(s3[i]);
}

// ---------------- rmsnorm (half output) ----------------
__global__ void rmsnorm_kernel(const float* __restrict__ x, const float* __restrict__ w,
                               __half* __restrict__ out, int cols, float eps) {
    int row = blockIdx.x;
    const float* xr = x + (size_t)row * cols;
    __half* orow = out + (size_t)row * cols;
    int per = cols >> 8;
    float xv[8];
    float ss = 0.f;
    for (int i = 0; i < per; i++) {
        float v = xr[threadIdx.x + (i << 8)];
        xv[i] = v; ss += v * v;
    }
    float tot = block_sum_256(ss);
    float scale = rsqrtf(tot / (float)cols + eps);
    for (int i = 0; i < per; i++) {
        int c = threadIdx.x + (i << 8);
        orow[c] = __float2half(xv[i] * scale * w[c]);
    }
}

// gated rmsnorm
__global__ void gated_rmsnorm_kernel(const __half* __restrict__ y, const float* __restrict__ zx,
                                     const float* __restrict__ w, __half* __restrict__ out) {
    int row = blockIdx.x;
    const __half* yr = y + (size_t)row * Ee;
    const float* zr = zx + (size_t)row * DIN;
    __half* orow = out + (size_t)row * Ee;
    float g[8];
    float ss = 0.f;
#pragma unroll
    for (int i = 0; i < 8; i++) {
        int c = threadIdx.x + (i << 8);
        float v = __half2float(yr[c]) * silu_f(zr[c]);
        g[i] = v; ss += v * v;
    }
    float tot = block_sum_256(ss);
    float scale = rsqrtf(tot / (float)Ee + NEPS);
#pragma unroll
    for (int i = 0; i < 8; i++) {
        int c = threadIdx.x + (i << 8);
        orow[c] = __float2half(g[i] * scale * w[c]);
    }
}

// ---------------- conv + silu (half output) ----------------
__global__ void conv_silu_kernel(const float* __restrict__ zx,
                                 const float* __restrict__ wc,
                                 const float* __restrict__ bcv,
                                 __half* __restrict__ xbc) {
    int idx = blockIdx.x * blockDim.x + threadIdx.x;
    if (idx >= TOK * CONVD) return;
    int t = idx / CONVD, c = idx - t * CONVD;
    int pos = t & (SEQL - 1);
    float s = bcv[c];
#pragma unroll
    for (int k = 0; k < Kc; k++) {
        int sp = pos - (Kc - 1) + k;
        if (sp >= 0)
            s += zx[(size_t)(t - (Kc - 1) + k) * DIN + Ee + c] * wc[c * Kc + k];
    }
    xbc[idx] = __float2half(silu_f(s));
}

// ---------------- dt softplus + per-chunk cumsum ----------------
__global__ void dtdacs_kernel(const float* __restrict__ zx, const float* __restrict__ dtb,
                              const float* __restrict__ alog,
                              float* __restrict__ dt, float* __restrict__ acs) {
    int bc = blockIdx.x, h = blockIdx.y;
    int tb = ((bc >> 4) << 11) + ((bc & 15) << 7);
    int q = threadIdx.x;
    int t = tb + q;
    float x = zx[(size_t)t * DIN + (Ee + CONVD) + h] + dtb[h];
    float d = (x > 20.f) ? x : log1pf(expf(x));
    dt[t * NHh + h] = d;
    float a = -expf(alog[h]);
    float v = d * a;
    int lane = q & 31;
#pragma unroll
    for (int o = 1; o < 32; o <<= 1) {
        float n = __shfl_up_sync(0xffffffffu, v, o);
        if (lane >= o) v += n;
    }
    __shared__ float ws[4];
    int wid = q >> 5;
    if (lane == 31) ws[wid] = v;
    __syncthreads();
    float add = 0.f;
    for (int w = 0; w < wid; w++) add += ws[w];
    acs[(bc * NHh + h) * Qq + q] = v + add;
}

// ================= SSD on tensor cores =================
#define SST 136

#define CS_DSMEM (192 * SST * 2 + 512)
__global__ __launch_bounds__(128) void chunk_states_mma(
    const __half* __restrict__ xbc, const float* __restrict__ dt,
    const float* __restrict__ acs, float* __restrict__ states) {
    extern __shared__ __half smh[];
    __half* Ah = smh;
    __half* Bh = smh + 64 * SST;
    float* wsh = (float*)(smh + 192 * SST);

    int bc = blockIdx.x, h = blockIdx.y;
    int tb = ((bc >> 4) << 11) + ((bc & 15) << 7);
    int tid = threadIdx.x, lane = tid & 31, wid = tid >> 5;
    int g = lane >> 2, tg = lane & 3;

    const float* ac = acs + (bc * NHh + h) * Qq;
    if (tid < 128) {
        float last = ac[127];
        wsh[tid] = __expf(last - ac[tid]) * dt[(tb + tid) * NHh + h];
    }
    __syncthreads();

    for (int i = tid; i < 64 * 128; i += 128) {
        int q = i >> 6, p = i & 63;
        float v = __half2float(xbc[(size_t)(tb + q) * CONVD + h * 64 + p]) * wsh[q];
        Ah[p * SST + q] = __float2half(v);
    }
    for (int i = tid; i < 128 * 128; i += 128) {
        int q = i >> 7, n = i & 127;
        Bh[n * SST + q] = xbc[(size_t)(tb + q) * CONVD + 2048 + n];
    }
    __syncthreads();

    int wm = (wid >> 1) << 5;
    int wn = (wid & 1) << 6;
    uint32_t abase = smem_u32(Ah), bbase = smem_u32(Bh);
    uint32_t aoff[2], boff[4];
#pragma unroll
    for (int mt = 0; mt < 2; mt++)
        aoff[mt] = abase + ((wm + (mt << 4) + (lane & 15)) * SST + ((lane >> 4) << 3)) * 2;
#pragma unroll
    for (int ntp = 0; ntp < 4; ntp++)
        boff[ntp] = bbase + ((wn + (ntp << 4) + (lane & 7) + (((lane >> 4) & 1) << 3)) * SST
                             + (((lane >> 3) & 1) << 3)) * 2;

    float acc[2][8][4] = {};
#pragma unroll
    for (int ks = 0; ks < 8; ks++) {
        uint32_t kb = ks << 5;
        uint32_t fa[2][4], fb[4][4];
#pragma unroll
        for (int mt = 0; mt < 2; mt++)
            ldsm_x4(fa[mt][0], fa[mt][1], fa[mt][2], fa[mt][3], aoff[mt] + kb);
#pragma unroll
        for (int ntp = 0; ntp < 4; ntp++)
            ldsm_x4(fb[ntp][0], fb[ntp][1], fb[ntp][2], fb[ntp][3], boff[ntp] + kb);
#pragma unroll
        for (int mt = 0; mt < 2; mt++)
#pragma unroll
            for (int nt = 0; nt < 8; nt++)
                mma_16816(acc[mt][nt], fa[mt],
                          fb[nt >> 1][((nt & 1) << 1)], fb[nt >> 1][((nt & 1) << 1) + 1]);
    }

    float* sp = states + (size_t)(bc * NHh + h) * 8192;
#pragma unroll
    for (int mt = 0; mt < 2; mt++) {
        int p = wm + (mt << 4) + g;
#pragma unroll
        for (int nt = 0; nt < 8; nt++) {
            int n = wn + (nt << 3) + (tg << 1);
            *(float2*)(sp + p * 128 + n) = make_float2(acc[mt][nt][0], acc[mt][nt][1]);
            *(float2*)(sp + (p + 8) * 128 + n) = make_float2(acc[mt][nt][2], acc[mt][nt][3]);
        }
    }
}

#define Y_DSMEM (192 * SST * 2 + 3 * 128 * 4)
__global__ __launch_bounds__(128) void y_mma_kernel(
    const __half* __restrict__ xbc, const float* __restrict__ dt,
    const float* __restrict__ acs, const float* __restrict__ prefix,
    const float* __restrict__ cb, const float* __restrict__ Dw,
    __half* __restrict__ y) {
    extern __shared__ __half smh[];
    __half* Ah = smh;
    __half* Bh = smh + 128 * SST;
    float* acs_s = (float*)(smh + 192 * SST);
    float* dts   = acs_s + 128;
    float* eqs   = dts + 128;

    int bc = blockIdx.x, h = blockIdx.y;
    int tb = ((bc >> 4) << 11) + ((bc & 15) << 7);
    int tid = threadIdx.x, lane = tid & 31, wid = tid >> 5;
    int g = lane >> 2, tg = lane & 3;

    if (tid < 128) {
        float a = acs[(bc * NHh + h) * Qq + tid];
        acs_s[tid] = a;
        eqs[tid] = __expf(a);
        dts[tid] = dt[(tb + tid) * NHh + h];
    }
    __syncthreads();

    const float* cbb = cb + (size_t)bc * 16384;
    for (int i = tid; i < 128 * 128; i += 128) {
        int q = i >> 7, s = i & 127;
        float v = (s <= q) ? cbb[q * 128 + s] * __expf(acs_s[q] - acs_s[s]) : 0.f;
        Ah[q * SST + s] = __float2half(v);
    }
    for (int i = tid; i < 64 * 128; i += 128) {
        int s = i >> 6, p = i & 63;
        float xv = __half2float(xbc[(size_t)(tb + s) * CONVD + h * 64 + p]);
        Bh[p * SST + s] = __float2half(xv * dts[s]);
    }
    __syncthreads();

    int wm = wid << 5;
    uint32_t abase = smem_u32(Ah), bbase = smem_u32(Bh);
    uint32_t aoff[2], boff[4];
#pragma unroll
    for (int mt = 0; mt < 2; mt++)
        aoff[mt] = abase + ((wm + (mt << 4) + (lane & 15)) * SST + ((lane >> 4) << 3)) * 2;
#pragma unroll
    for (int ntp = 0; ntp < 4; ntp++)
        boff[ntp] = bbase + (((ntp << 4) + (lane & 7) + (((lane >> 4) & 1) << 3)) * SST
                             + (((lane >> 3) & 1) << 3)) * 2;

    float acc[2][8][4] = {};
    auto run_phase = [&]() {
#pragma unroll
        for (int ks = 0; ks < 8; ks++) {
            uint32_t kb = ks << 5;
            uint32_t fa[2][4], fb[4][4];
#pragma unroll
            for (int mt = 0; mt < 2; mt++)
                ldsm_x4(fa[mt][0], fa[mt][1], fa[mt][2], fa[mt][3], aoff[mt] + kb);
#pragma unroll
            for (int ntp = 0; ntp < 4; ntp++)
                ldsm_x4(fb[ntp][0], fb[ntp][1], fb[ntp][2], fb[ntp][3], boff[ntp] + kb);
#pragma unroll
            for (int mt = 0; mt < 2; mt++)
#pragma unroll
                for (int nt = 0; nt < 8; nt++)
                    mma_16816(acc[mt][nt], fa[mt],
                              fb[nt >> 1][((nt & 1) << 1)], fb[nt >> 1][((nt & 1) << 1) + 1]);
        }
    };
    run_phase();
    __syncthreads();

    for (int i = tid; i < 128 * 128; i += 128) {
        int q = i >> 7, n = i & 127;
        float cv = __half2float(xbc[(size_t)(tb + q) * CONVD + 2176 + n]);
        Ah[q * SST + n] = __float2half(cv * eqs[q]);
    }
    const float* pref = prefix + (size_t)(bc * NHh + h) * 8192;
    for (int i = tid; i < 64 * 128; i += 128) {
        int p = i >> 7, n = i & 127;
        Bh[p * SST + n] = __float2half(pref[p * 128 + n]);
    }
    __syncthreads();
    run_phase();

    float Dh = Dw[h];
#pragma unroll
    for (int mt = 0; mt < 2; mt++) {
        int q = wm + (mt << 4) + g;
#pragma unroll
        for (int nt = 0; nt < 8; nt++) {
            int p = (nt << 3) + (tg << 1);
            {
                int t = tb + q;
                float2 xv = __half22float2(*(const __half2*)(xbc + (size_t)t * CONVD + h * 64 + p));
                *(__half2*)(y + (size_t)t * Ee + h * 64 + p) =
                    __floats2half2_rn(acc[mt][nt][0] + Dh * xv.x, acc[mt][nt][1] + Dh * xv.y);
            }
            {
                int t = tb + q + 8;
                float2 xv = __half22float2(*(const __half2*)(xbc + (size_t)t * CONVD + h * 64 + p));
                *(__half2*)(y + (size_t)t * Ee + h * 64 + p) =
                    __floats2half2_rn(acc[mt][nt][2] + Dh * xv.x, acc[mt][nt][3] + Dh * xv.y);
            }
        }
    }
}

// ---------------- inter-chunk recurrence (split 4x over columns) ----------------
__global__ void chunk_scan_kernel(const float* __restrict__ states,
                                  const float* __restrict__ acs,
                                  float* __restrict__ prefix) {
    int b = blockIdx.x, h = blockIdx.y, seg = blockIdx.z;
    int tid = threadIdx.x;
    int base_e = seg * 2048;
    float run[8];
#pragma unroll
    for (int i = 0; i < 8; i++) run[i] = 0.f;
    for (int ch = 0; ch < 16; ch++) {
        int bc = b * 16 + ch;
        size_t base = (size_t)(bc * NHh + h) * 8192 + base_e;
        float al = expf(acs[(bc * NHh + h) * Qq + 127]);
#pragma unroll
        for (int i = 0; i < 8; i++) {
            int e = (i << 8) + tid;
            prefix[base + e] = run[i];
            run[i] = run[i] * al + states[base + e];
        }
    }
}

// ---------------- CB (split over q; half input) ----------------
__global__ __launch_bounds__(256) void cb_kernel(const __half* __restrict__ xbc,
                                                 float* __restrict__ cbout) {
    int bc = blockIdx.x;
    int q0 = blockIdx.y << 6;
    int tb = ((bc >> 4) << 11) + ((bc & 15) << 7);
    __shared__ float Ct[64][33];
    __shared__ float Bt[128][33];
    int tid = threadIdx.x;
    int tq = tid >> 4, ts = tid & 15;
    float acc[4][8] = {};
    for (int nt = 0; nt < 128; nt += 32) {
        for (int i = tid; i < 2048; i += 256) {
            int r = i >> 5, nn = i & 31;
            Ct[r][nn] = __half2float(xbc[(size_t)(tb + q0 + r) * CONVD + 2176 + nt + nn]);
        }
        for (int i = tid; i < 4096; i += 256) {
            int r = i >> 5, nn = i & 31;
            Bt[r][nn] = __half2float(xbc[(size_t)(tb + r) * CONVD + 2048 + nt + nn]);
        }
        __syncthreads();
        for (int nn = 0; nn < 32; nn++) {
            float ca[4], bb[8];
#pragma unroll
            for (int i = 0; i < 4; i++) ca[i] = Ct[tq * 4 + i][nn];
#pragma unroll
            for (int j = 0; j < 8; j++) bb[j] = Bt[ts * 8 + j][nn];
#pragma unroll
            for (int i = 0; i < 4; i++)
#pragma unroll
                for (int j = 0; j < 8; j++) acc[i][j] += ca[i] * bb[j];
        }
        __syncthreads();
    }
    float* o = cbout + (size_t)bc * 16384;
#pragma unroll
    for (int i = 0; i < 4; i++)
#pragma unroll
        for (int j = 0; j < 8; j++)
            o[(q0 + tq * 4 + i) * 128 + ts * 8 + j] = acc[i][j];
}

// ---------------- host launcher ----------------
extern "C" void kernel_launch(void* const* d_in, const int* in_sizes, int n_in,
                              void* d_out, int out_size) {
    const float* hid   = (const float*)d_in[0];
    const float* wln1  = (const float*)d_in[1];
    const float* win   = (const float*)d_in[2];
    const float* wconv = (const float*)d_in[3];
    const float* bcv   = (const float*)d_in[4];
    const float* dtb   = (const float*)d_in[5];
    const float* alog  = (const float*)d_in[6];
    const float* Dw    = (const float*)d_in[7];
    const float* wmn   = (const float*)d_in[8];
    const float* wout  = (const float*)d_in[9];
    const float* wln2  = (const float*)d_in[10];
    const float* wg    = (const float*)d_in[11];
    const float* wu    = (const float*)d_in[12];
    const float* wd    = (const float*)d_in[13];
    float* out = (float*)d_out;

    __half *hnorm, *xbch, *yh, *y2, *h2n, *ggh, *gu, *wh_in, *wh_out, *wh_g, *wh_u, *wh_d;
    float *zx, *dt, *acs, *states, *prefix, *cbp, *hid2;
    cudaGetSymbolAddress((void**)&hnorm,  g_hnorm);
    cudaGetSymbolAddress((void**)&zx,     g_zx);
    cudaGetSymbolAddress((void**)&xbch,   g_xbch);
    cudaGetSymbolAddress((void**)&dt,     g_dt);
    cudaGetSymbolAddress((void**)&acs,    g_acs);
    cudaGetSymbolAddress((void**)&states, g_states);
    cudaGetSymbolAddress((void**)&prefix, g_prefix);
    cudaGetSymbolAddress((void**)&cbp,    g_cb);
    cudaGetSymbolAddress((void**)&yh,     g_yh);
    cudaGetSymbolAddress((void**)&y2,     g_y2);
    cudaGetSymbolAddress((void**)&hid2,   g_hid2);
    cudaGetSymbolAddress((void**)&h2n,    g_h2n);
    cudaGetSymbolAddress((void**)&ggh,    g_gateh);
    cudaGetSymbolAddress((void**)&gu,     g_gu);
    cudaGetSymbolAddress((void**)&wh_in,  g_wh_in);
    cudaGetSymbolAddress((void**)&wh_out, g_wh_out);
    cudaGetSymbolAddress((void**)&wh_g,   g_wh_g);
    cudaGetSymbolAddress((void**)&wh_u,   g_wh_u);
    cudaGetSymbolAddress((void**)&wh_d,   g_wh_d);

    cudaFuncSetAttribute(mma_gemm<0>, cudaFuncAttributeMaxDynamicSharedMemorySize, GEMM_DSMEM);
    cudaFuncSetAttribute(mma_gemm<1>, cudaFuncAttributeMaxDynamicSharedMemorySize, GEMM_DSMEM);
    cudaFuncSetAttribute(mma_gemm<2>, cudaFuncAttributeMaxDynamicSharedMemorySize, GEMM_DSMEM);
    cudaFuncSetAttribute(mma_gemm<3>, cudaFuncAttributeMaxDynamicSharedMemorySize, GEMM_DSMEM);
    cudaFuncSetAttribute(chunk_states_mma, cudaFuncAttributeMaxDynamicSharedMemorySize, CS_DSMEM);
    cudaFuncSetAttribute(y_mma_kernel, cudaFuncAttributeMaxDynamicSharedMemorySize, Y_DSMEM);

    // 0) in-proj weights -> fp16
    round_h4_kernel<<<(DIN * Hh / 4 + 255) / 256, 256>>>((const float4*)win, (uint2*)wh_in, DIN * Hh / 4);
    // 1) pre-norm
    rmsnorm_kernel<<<TOK, 256>>>(hid, wln1, hnorm, Hh, EPS1);
    // 2) in-projection
    mma_gemm<0><<<dim3((DIN + 127) / 128, TOK / 128), 256, GEMM_DSMEM>>>(hnorm, wh_in, nullptr, zx, nullptr, TOK, DIN, Hh, 0);
    // 3) conv + silu
    conv_silu_kernel<<<(TOK * CONVD + 255) / 256, 256>>>(zx, wconv, bcv, xbch);
    // 4) dt + cumsum
    dtdacs_kernel<<<dim3(NCHUNK, NHh), 128>>>(zx, dtb, alog, dt, acs);
    // 5) chunk states (mma)
    chunk_states_mma<<<dim3(NCHUNK, NHh), 128, CS_DSMEM>>>(xbch, dt, acs, states);
    // 6) scan (4x column split)
    chunk_scan_kernel<<<dim3(2, NHh, 4), 256>>>(states, acs, prefix);
    // 7) CB
    cb_kernel<<<dim3(NCHUNK, 2), 256>>>(xbch, cbp);
    // 8) Y (mma)
    y_mma_kernel<<<dim3(NCHUNK, NHh), 128, Y_DSMEM>>>(xbch, dt, acs, prefix, cbp, Dw, yh);
    // 9) remaining weights -> fp16
    {
        int ntot = (Hh * Ee + FFd * Hh + FFd * Hh + Hh * FFd) / 4;
        round4v_kernel<<<(ntot + 255) / 256, 256>>>(
            (const float4*)wout, (uint2*)wh_out, Hh * Ee / 4,
            (const float4*)wg,   (uint2*)wh_g,   FFd * Hh / 4,
            (const float4*)wu,   (uint2*)wh_u,   FFd * Hh / 4,
            (const float4*)wd,   (uint2*)wh_d,   Hh * FFd / 4);
    }
    // 10) gated norm
    gated_rmsnorm_kernel<<<TOK, 256>>>(yh, zx, wmn, y2);
    // 11) out-proj + residual
    mma_gemm<1><<<dim3(Hh / 128, TOK / 128), 256, GEMM_DSMEM>>>(y2, wh_out, hid, hid2, nullptr, TOK, Hh, Ee, 0);
    // 12) norm 2
    rmsnorm_kernel<<<TOK, 256>>>(hid2, wln2, h2n, Hh, EPS1);
    // 13) gate projection (half out)
    mma_gemm<3><<<dim3(FFd / 128, TOK / 128), 256, GEMM_DSMEM>>>(h2n, wh_g, nullptr, nullptr, ggh, TOK, FFd, Hh, 0);
    // 14) up projection + fused silu(gate)*up
    mma_gemm<2><<<dim3(FFd / 128, TOK / 128), 256, GEMM_DSMEM>>>(h2n, wh_u, ggh, nullptr, gu, TOK, FFd, Hh, 0);
    // 15) down + residual -> output
    mma_gemm<1><<<dim3(Hh / 128, TOK / 128), 256, GEMM_DSMEM>>>(gu, wh_d, hid2, out, nullptr, TOK, Hh, FFd, 0);
}

// round 16
// speedup vs baseline: 1.2055x; 1.0210x over previous
#include <cuda_runtime.h>
#include <cuda_fp16.h>
#include <cstdint>
#include <math.h>

// ---------------- problem dims ----------------
#define TOK   4096
#define SEQL  2048
#define Hh    1024
#define Ee    2048
#define NHh   32
#define Nn    128
#define Qq    128
#define Kc    4
#define CONVD 2304
#define DIN   4384
#define FFd   4096
#define NCHUNK 32
#define EPS1  1e-6f
#define NEPS  1e-5f

// ---------------- scratch ----------------
__device__ __half g_hnorm [TOK * Hh];
__device__ float  g_zx    [TOK * DIN];
__device__ __half g_zh    [TOK * Ee];
__device__ __half g_xbch  [TOK * CONVD];
__device__ float  g_dt    [TOK * NHh];
__device__ float  g_acs   [NCHUNK * NHh * Qq];
__device__ float  g_states[NCHUNK * NHh * 64 * Nn];
__device__ float  g_prefix[NCHUNK * NHh * 64 * Nn];
__device__ float  g_cb    [NCHUNK * Qq * Qq];
__device__ __half g_yh    [TOK * Ee];
__device__ __half g_y2    [TOK * Ee];
__device__ float  g_hid2  [TOK * Hh];
__device__ __half g_h2n   [TOK * Hh];
__device__ __half g_gateh [TOK * FFd];
__device__ __half g_gu    [TOK * FFd];
// fp16 weights
__device__ __half g_wh_in [DIN * Hh];
__device__ __half g_wh_out[Hh * Ee];
__device__ __half g_wh_g  [FFd * Hh];
__device__ __half g_wh_u  [FFd * Hh];
__device__ __half g_wh_d  [Hh * FFd];

// ---------------- helpers ----------------
__device__ __forceinline__ uint32_t smem_u32(const void* p) {
    return (uint32_t)__cvta_generic_to_shared(p);
}
__device__ __forceinline__ float silu_f(float x) { return x / (1.f + expf(-x)); }
__device__ __forceinline__ float block_sum_256(float v) {
    __shared__ float sh[8];
    __syncthreads();
    int lane = threadIdx.x & 31, wid = threadIdx.x >> 5;
#pragma unroll
    for (int o = 16; o > 0; o >>= 1) v += __shfl_down_sync(0xffffffffu, v, o);
    if (lane == 0) sh[wid] = v;
    __syncthreads();
    if (threadIdx.x == 0) {
        float s = 0.f;
#pragma unroll
        for (int i = 0; i < 8; i++) s += sh[i];
        sh[0] = s;
    }
    __syncthreads();
    return sh[0];
}
__device__ __forceinline__ void cp_async16(uint32_t dst, const void* src, int sz) {
    asm volatile("cp.async.cg.shared.global [%0], [%1], 16, %2;"
                 :: "r"(dst), "l"((unsigned long long)__cvta_generic_to_global(src)), "r"(sz)
                 : "memory");
}
__device__ __forceinline__ void ldsm_x4(uint32_t& r0, uint32_t& r1, uint32_t& r2, uint32_t& r3,
                                        uint32_t addr) {
    asm volatile("ldmatrix.sync.aligned.m8n8.x4.shared.b16 {%0,%1,%2,%3}, [%4];"
                 : "=r"(r0), "=r"(r1), "=r"(r2), "=r"(r3) : "r"(addr));
}
__device__ __forceinline__ uint2 f4_to_h4(float4 v) {
    __half2 lo = __floats2half2_rn(v.x, v.y);
    __half2 hi = __floats2half2_rn(v.z, v.w);
    return make_uint2(*(uint32_t*)&lo, *(uint32_t*)&hi);
}
__device__ __forceinline__ void mma_16816(float* a4, const uint32_t* fa, uint32_t b0, uint32_t b1) {
    asm volatile(
        "mma.sync.aligned.m16n8k16.row.col.f32.f16.f16.f32 "
        "{%0,%1,%2,%3}, {%4,%5,%6,%7}, {%8,%9}, {%0,%1,%2,%3};"
        : "+f"(a4[0]), "+f"(a4[1]), "+f"(a4[2]), "+f"(a4[3])
        : "r"(fa[0]), "r"(fa[1]), "r"(fa[2]), "r"(fa[3]), "r"(b0), "r"(b1));
}

// ---------------- fp16 mma.sync GEMM (128x128, 5-stage, 2 CTA/SM) ----------------
// MODE: 0 = in-proj split store (cc<2048 half->Ch stride Ee, else f32->Cf stride N)
//       1 = f32 store + f32 addsrc, 2 = half silu(half aux)*acc, 3 = half store
#define GSTAGES 5
#define LDSTH 40
#define STAGE_HALVES (256 * LDSTH)
#define STAGE_BYTES  (STAGE_HALVES * 2)
#define GEMM_DSMEM (GSTAGES * STAGE_BYTES)

template<int MODE>
__global__ __launch_bounds__(256, 2) void mma_gemm(
    const __half* __restrict__ A, const __half* __restrict__ B,
    const void* __restrict__ aux, float* __restrict__ Cf, __half* __restrict__ Ch,
    int M, int N, int K, int col_base)
{
    extern __shared__ __half smh[];
    int tid = threadIdx.x;
    int lane = tid & 31, wid = tid >> 5;
    int g = lane >> 2, tg = lane & 3;
    int wm = (wid >> 1) << 5;
    int wn = (wid & 1) << 6;
    int row0 = blockIdx.y << 7, col0 = (blockIdx.x << 7) + col_base;
    int NC = K >> 5;
    uint32_t smbase = smem_u32(smh);

    uint32_t aoff[2], boff[4];
#pragma unroll
    for (int mt = 0; mt < 2; mt++)
        aoff[mt] = ((wm + (mt << 4) + (lane & 15)) * LDSTH + ((lane >> 4) << 3)) * 2;
#pragma unroll
    for (int ntp = 0; ntp < 4; ntp++)
        boff[ntp] = (128 * LDSTH + (wn + (ntp << 4) + (lane & 7) + (((lane >> 4) & 1) << 3)) * LDSTH
                     + (((lane >> 3) & 1) << 3)) * 2;

    float acc[2][8][4];
#pragma unroll
    for (int i = 0; i < 2; i++)
#pragma unroll
        for (int j = 0; j < 8; j++)
#pragma unroll
            for (int k = 0; k < 4; k++) acc[i][j][k] = 0.f;

    auto load_stage = [&](int s, int c) {
        __half* As = smh + s * STAGE_HALVES;
        __half* Bs = As + 128 * LDSTH;
        const __half* Ag = A + (size_t)row0 * K + (c << 5);
        const __half* Bg = B + (size_t)col0 * K + (c << 5);
#pragma unroll
        for (int it = 0; it < 4; it++) {
            int i = tid + (it << 8);
            if (i < 512) {
                int r = i >> 2, c8 = (i & 3) << 3;
                cp_async16(smem_u32(As + r * LDSTH + c8), Ag + (size_t)r * K + c8, 16);
            } else {
                int j = i - 512;
                int r = j >> 2, c8 = (j & 3) << 3;
                int sz = (col0 + r < N) ? 16 : 0;
                cp_async16(smem_u32(Bs + r * LDSTH + c8), Bg + (size_t)r * K + c8, sz);
            }
        }
    };

    uint32_t fa0[2][4], fb0[4][4], fa1[2][4], fb1[4][4];

    auto load_frags = [&](uint32_t (&fa)[2][4], uint32_t (&fb)[4][4], uint32_t stb, int ks) {
        uint32_t kb = stb + (ks << 5);
#pragma unroll
        for (int mt = 0; mt < 2; mt++)
            ldsm_x4(fa[mt][0], fa[mt][1], fa[mt][2], fa[mt][3], kb + aoff[mt]);
#pragma unroll
        for (int ntp = 0; ntp < 4; ntp++)
            ldsm_x4(fb[ntp][0], fb[ntp][1], fb[ntp][2], fb[ntp][3], kb + boff[ntp]);
    };
    auto do_mma = [&](uint32_t (&fa)[2][4], uint32_t (&fb)[4][4]) {
#pragma unroll
        for (int mt = 0; mt < 2; mt++)
#pragma unroll
            for (int nt = 0; nt < 8; nt++)
                mma_16816(acc[mt][nt], fa[mt],
                          fb[nt >> 1][((nt & 1) << 1)], fb[nt >> 1][((nt & 1) << 1) + 1]);
    };

#pragma unroll
    for (int s = 0; s < GSTAGES - 1; s++) {
        load_stage(s, s);
        asm volatile("cp.async.commit_group;" ::: "memory");
    }
    asm volatile("cp.async.wait_group %0;" :: "n"(GSTAGES - 2) : "memory");
    __syncthreads();
    load_frags(fa0, fb0, smbase, 0);

    for (int c = 0; c < NC; c++) {
        int nxt = c + GSTAGES - 1;
        if (nxt < NC) load_stage(nxt % GSTAGES, nxt);
        asm volatile("cp.async.commit_group;" ::: "memory");

        uint32_t stb = smbase + (c % GSTAGES) * STAGE_BYTES;
        load_frags(fa1, fb1, stb, 1);
        do_mma(fa0, fb0);

        if (c + 1 < NC) {
            asm volatile("cp.async.wait_group %0;" :: "n"(GSTAGES - 2) : "memory");
            __syncthreads();
            load_frags(fa0, fb0, smbase + ((c + 1) % GSTAGES) * STAGE_BYTES, 0);
        }
        do_mma(fa1, fb1);
    }

    // epilogue
#pragma unroll
    for (int mt = 0; mt < 2; mt++) {
        int r = row0 + wm + (mt << 4) + g;
#pragma unroll
        for (int nt = 0; nt < 8; nt++) {
            int cc = col0 + wn + (nt << 3) + (tg << 1);
            if (cc >= N) continue;
            float v0 = acc[mt][nt][0], v1 = acc[mt][nt][1];
            float v2 = acc[mt][nt][2], v3 = acc[mt][nt][3];
            if (MODE == 0) {
                if (cc < Ee) {
                    *(__half2*)(Ch + (size_t)r * Ee + cc) = __floats2half2_rn(v0, v1);
                    *(__half2*)(Ch + (size_t)(r + 8) * Ee + cc) = __floats2half2_rn(v2, v3);
                } else {
                    *(float2*)(Cf + (size_t)r * N + cc) = make_float2(v0, v1);
                    *(float2*)(Cf + (size_t)(r + 8) * N + cc) = make_float2(v2, v3);
                }
            } else if (MODE == 1) {
                const float* af = (const float*)aux;
                float2 s0 = *(const float2*)(af + (size_t)r * N + cc);
                float2 s1 = *(const float2*)(af + (size_t)(r + 8) * N + cc);
                *(float2*)(Cf + (size_t)r * N + cc) = make_float2(v0 + s0.x, v1 + s0.y);
                *(float2*)(Cf + (size_t)(r + 8) * N + cc) = make_float2(v2 + s1.x, v3 + s1.y);
            } else if (MODE == 2) {
                const __half* ah = (const __half*)aux;
                float2 gf0 = __half22float2(*(const __half2*)(ah + (size_t)r * N + cc));
                float2 gf1 = __half22float2(*(const __half2*)(ah + (size_t)(r + 8) * N + cc));
                *(__half2*)(Ch + (size_t)r * N + cc) =
                    __floats2half2_rn(silu_f(gf0.x) * v0, silu_f(gf0.y) * v1);
                *(__half2*)(Ch + (size_t)(r + 8) * N + cc) =
                    __floats2half2_rn(silu_f(gf1.x) * v2, silu_f(gf1.y) * v3);
            } else {
                *(__half2*)(Ch + (size_t)r * N + cc) = __floats2half2_rn(v0, v1);
                *(__half2*)(Ch + (size_t)(r + 8) * N + cc) = __floats2half2_rn(v2, v3);
            }
        }
    }
}

// ---------------- weight fp16 conversions ----------------
__global__ void round_h4_kernel(const float4* __restrict__ in, uint2* __restrict__ out, int n4) {
    int i = blockIdx.x * blockDim.x + threadIdx.x;
    if (i < n4) out[i] = f4_to_h4(in[i]);
}
__global__ void round4v_kernel(const float4* __restrict__ s0, uint2* __restrict__ d0, int n0,
                               const float4* __restrict__ s1, uint2* __restrict__ d1, int n1,
                               const float4* __restrict__ s2, uint2* __restrict__ d2, int n2,
                               const float4* __restrict__ s3, uint2* __restrict__ d3, int n3) {
    int i = blockIdx.x * blockDim.x + threadIdx.x;
    if (i < n0) { d0[i] = f4_to_h4(s0[i]); return; }
    i -= n0;
    if (i < n1) { d1[i] = f4_to_h4(s1[i]); return; }
    i -= n1;
    if (i < n2) { d2[i] = f4_to_h4(s2[i]); return; }
    i -= n2;
    if (i < n3) d3[i] = f4_to_h4(s3[i]);
}

// ---------------- rmsnorm (half output) ----------------
__global__ void rmsnorm_kernel(const float* __restrict__ x, const float* __restrict__ w,
                               __half* __restrict__ out, int cols, float eps) {
    int row = blockIdx.x;
    const float* xr = x + (size_t)row * cols;
    __half* orow = out + (size_t)row * cols;
    int per = cols >> 8;
    float xv[8];
    float ss = 0.f;
    for (int i = 0; i < per; i++) {
        float v = xr[threadIdx.x + (i << 8)];
        xv[i] = v; ss += v * v;
    }
    float tot = block_sum_256(ss);
    float scale = rsqrtf(tot / (float)cols + eps);
    for (int i = 0; i < per; i++) {
        int c = threadIdx.x + (i << 8);
        orow[c] = __float2half(xv[i] * scale * w[c]);
    }
}

// gated rmsnorm: y fp16, z fp16 (stride Ee)
__global__ void gated_rmsnorm_kernel(const __half* __restrict__ y, const __half* __restrict__ zh,
                                     const float* __restrict__ w, __half* __restrict__ out) {
    int row = blockIdx.x;
    const __half* yr = y + (size_t)row * Ee;
    const __half* zr = zh + (size_t)row * Ee;
    __half* orow = out + (size_t)row * Ee;
    float g[8];
    float ss = 0.f;
#pragma unroll
    for (int i = 0; i < 8; i++) {
        int c = threadIdx.x + (i << 8);
        float v = __half2float(yr[c]) * silu_f(__half2float(zr[c]));
        g[i] = v; ss += v * v;
    }
    float tot = block_sum_256(ss);
    float scale = rsqrtf(tot / (float)Ee + NEPS);
#pragma unroll
    for (int i = 0; i < 8; i++) {
        int c = threadIdx.x + (i << 8);
        orow[c] = __float2half(g[i] * scale * w[c]);
    }
}

// ---------------- conv + silu: 4 timesteps/thread ----------------
__global__ void conv_silu4t_kernel(const float* __restrict__ zx,
                                   const float4* __restrict__ wc4,
                                   const float* __restrict__ bcv,
                                   __half* __restrict__ xbc) {
    int idx = blockIdx.x * blockDim.x + threadIdx.x;
    if (idx >= (TOK / 4) * CONVD) return;
    int tq = idx / CONVD, c = idx - tq * CONVD;
    int t0 = tq << 2;
    int pos0 = t0 & (SEQL - 1);
    float4 w = wc4[c];
    float b = bcv[c];
    float z[7];
#pragma unroll
    for (int j = 0; j < 3; j++)
        z[j] = (pos0 + j - 3 >= 0) ? zx[(size_t)(t0 + j - 3) * DIN + Ee + c] : 0.f;
#pragma unroll
    for (int j = 3; j < 7; j++)
        z[j] = zx[(size_t)(t0 + j - 3) * DIN + Ee + c];
#pragma unroll
    for (int i = 0; i < 4; i++) {
        float s = b + w.x * z[i] + w.y * z[i + 1] + w.z * z[i + 2] + w.w * z[i + 3];
        xbc[(size_t)(t0 + i) * CONVD + c] = __float2half(silu_f(s));
    }
}

// ---------------- dt softplus + per-chunk cumsum ----------------
__global__ void dtdacs_kernel(const float* __restrict__ zx, const float* __restrict__ dtb,
                              const float* __restrict__ alog,
                              float* __restrict__ dt, float* __restrict__ acs) {
    int bc = blockIdx.x, h = blockIdx.y;
    int tb = ((bc >> 4) << 11) + ((bc & 15) << 7);
    int q = threadIdx.x;
    int t = tb + q;
    float x = zx[(size_t)t * DIN + (Ee + CONVD) + h] + dtb[h];
    float d = (x > 20.f) ? x : log1pf(expf(x));
    dt[t * NHh + h] = d;
    float a = -expf(alog[h]);
    float v = d * a;
    int lane = q & 31;
#pragma unroll
    for (int o = 1; o < 32; o <<= 1) {
        float n = __shfl_up_sync(0xffffffffu, v, o);
        if (lane >= o) v += n;
    }
    __shared__ float ws[4];
    int wid = q >> 5;
    if (lane == 31) ws[wid] = v;
    __syncthreads();
    float add = 0.f;
    for (int w = 0; w < wid; w++) add += ws[w];
    acs[(bc * NHh + h) * Qq + q] = v + add;
}

// ================= SSD on tensor cores =================
#define SST 136

#define CS_DSMEM (192 * SST * 2 + 512)
__global__ __launch_bounds__(128) void chunk_states_mma(
    const __half* __restrict__ xbc, const float* __restrict__ dt,
    const float* __restrict__ acs, float* __restrict__ states) {
    extern __shared__ __half smh[];
    __half* Ah = smh;
    __half* Bh = smh + 64 * SST;
    float* wsh = (float*)(smh + 192 * SST);

    int bc = blockIdx.x, h = blockIdx.y;
    int tb = ((bc >> 4) << 11) + ((bc & 15) << 7);
    int tid = threadIdx.x, lane = tid & 31, wid = tid >> 5;
    int g = lane >> 2, tg = lane & 3;

    const float* ac = acs + (bc * NHh + h) * Qq;
    if (tid < 128) {
        float last = ac[127];
        wsh[tid] = __expf(last - ac[tid]) * dt[(tb + tid) * NHh + h];
    }
    __syncthreads();

    for (int i = tid; i < 64 * 128; i += 128) {
        int q = i >> 6, p = i & 63;
        float v = __half2float(xbc[(size_t)(tb + q) * CONVD + h * 64 + p]) * wsh[q];
        Ah[p * SST + q] = __float2half(v);
    }
    for (int i = tid; i < 128 * 128; i += 128) {
        int q = i >> 7, n = i & 127;
        Bh[n * SST + q] = xbc[(size_t)(tb + q) * CONVD + 2048 + n];
    }
    __syncthreads();

    int wm = (wid >> 1) << 5;
    int wn = (wid & 1) << 6;
    uint32_t abase = smem_u32(Ah), bbase = smem_u32(Bh);
    uint32_t aoff[2], boff[4];
#pragma unroll
    for (int mt = 0; mt < 2; mt++)
        aoff[mt] = abase + ((wm + (mt << 4) + (lane & 15)) * SST + ((lane >> 4) << 3)) * 2;
#pragma unroll
    for (int ntp = 0; ntp < 4; ntp++)
        boff[ntp] = bbase + ((wn + (ntp << 4) + (lane & 7) + (((lane >> 4) & 1) << 3)) * SST
                             + (((lane >> 3) & 1) << 3)) * 2;

    float acc[2][8][4] = {};
#pragma unroll
    for (int ks = 0; ks < 8; ks++) {
        uint32_t kb = ks << 5;
        uint32_t fa[2][4], fb[4][4];
#pragma unroll
        for (int mt = 0; mt < 2; mt++)
            ldsm_x4(fa[mt][0], fa[mt][1], fa[mt][2], fa[mt][3], aoff[mt] + kb);
#pragma unroll
        for (int ntp = 0; ntp < 4; ntp++)
            ldsm_x4(fb[ntp][0], fb[ntp][1], fb[ntp][2], fb[ntp][3], boff[ntp] + kb);
#pragma unroll
        for (int mt = 0; mt < 2; mt++)
#pragma unroll
            for (int nt = 0; nt < 8; nt++)
                mma_16816(acc[mt][nt], fa[mt],
                          fb[nt >> 1][((nt & 1) << 1)], fb[nt >> 1][((nt & 1) << 1) + 1]);
    }

    float* sp = states + (size_t)(bc * NHh + h) * 8192;
#pragma unroll
    for (int mt = 0; mt < 2; mt++) {
        int p = wm + (mt << 4) + g;
#pragma unroll
        for (int nt = 0; nt < 8; nt++) {
            int n = wn + (nt << 3) + (tg << 1);
            *(float2*)(sp + p * 128 + n) = make_float2(acc[mt][nt][0], acc[mt][nt][1]);
            *(float2*)(sp + (p + 8) * 128 + n) = make_float2(acc[mt][nt][2], acc[mt][nt][3]);
        }
    }
}

#define Y_DSMEM (192 * SST * 2 + 3 * 128 * 4)
__global__ __launch_bounds__(128) void y_mma_kernel(
    const __half* __restrict__ xbc, const float* __restrict__ dt,
    const float* __restrict__ acs, const float* __restrict__ prefix,
    const float* __restrict__ cb, const float* __restrict__ Dw,
    __half* __restrict__ y) {
    extern __shared__ __half smh[];
    __half* Ah = smh;
    __half* Bh = smh + 128 * SST;
    float* acs_s = (float*)(smh + 192 * SST);
    float* dts   = acs_s + 128;
    float* eqs   = dts + 128;

    int bc = blockIdx.x, h = blockIdx.y;
    int tb = ((bc >> 4) << 11) + ((bc & 15) << 7);
    int tid = threadIdx.x, lane = tid & 31, wid = tid >> 5;
    int g = lane >> 2, tg = lane & 3;

    if (tid < 128) {
        float a = acs[(bc * NHh + h) * Qq + tid];
        acs_s[tid] = a;
        eqs[tid] = __expf(a);
        dts[tid] = dt[(tb + tid) * NHh + h];
    }
    __syncthreads();

    const float* cbb = cb + (size_t)bc * 16384;
    for (int i = tid; i < 128 * 128; i += 128) {
        int q = i >> 7, s = i & 127;
        float v = (s <= q) ? cbb[q * 128 + s] * __expf(acs_s[q] - acs_s[s]) : 0.f;
        Ah[q * SST + s] = __float2half(v);
    }
    for (int i = tid; i < 64 * 128; i += 128) {
        int s = i >> 6, p = i & 63;
        float xv = __half2float(xbc[(size_t)(tb + s) * CONVD + h * 64 + p]);
        Bh[p * SST + s] = __float2half(xv * dts[s]);
    }
    __syncthreads();

    int wm = wid << 5;
    uint32_t abase = smem_u32(Ah), bbase = smem_u32(Bh);
    uint32_t aoff[2], boff[4];
#pragma unroll
    for (int mt = 0; mt < 2; mt++)
        aoff[mt] = abase + ((wm + (mt << 4) + (lane & 15)) * SST + ((lane >> 4) << 3)) * 2;
#pragma unroll
    for (int ntp = 0; ntp < 4; ntp++)
        boff[ntp] = bbase + (((ntp << 4) + (lane & 7) + (((lane >> 4) & 1) << 3)) * SST
                             + (((lane >> 3) & 1) << 3)) * 2;

    float acc[2][8][4] = {};
    auto run_phase = [&]() {
#pragma unroll
        for (int ks = 0; ks < 8; ks++) {
            uint32_t kb = ks << 5;
            uint32_t fa[2][4], fb[4][4];
#pragma unroll
            for (int mt = 0; mt < 2; mt++)
                ldsm_x4(fa[mt][0], fa[mt][1], fa[mt][2], fa[mt][3], aoff[mt] + kb);
#pragma unroll
            for (int ntp = 0; ntp < 4; ntp++)
                ldsm_x4(fb[ntp][0], fb[ntp][1], fb[ntp][2], fb[ntp][3], boff[ntp] + kb);
#pragma unroll
            for (int mt = 0; mt < 2; mt++)
#pragma unroll
                for (int nt = 0; nt < 8; nt++)
                    mma_16816(acc[mt][nt], fa[mt],
                              fb[nt >> 1][((nt & 1) << 1)], fb[nt >> 1][((nt & 1) << 1) + 1]);
        }
    };
    run_phase();
    __syncthreads();

    for (int i = tid; i < 128 * 128; i += 128) {
        int q = i >> 7, n = i & 127;
        float cv = __half2float(xbc[(size_t)(tb + q) * CONVD + 2176 + n]);
        Ah[q * SST + n] = __float2half(cv * eqs[q]);
    }
    const float* pref = prefix + (size_t)(bc * NHh + h) * 8192;
    for (int i = tid; i < 64 * 128; i += 128) {
        int p = i >> 7, n = i & 127;
        Bh[p * SST + n] = __float2half(pref[p * 128 + n]);
    }
    __syncthreads();
    run_phase();

    float Dh = Dw[h];
#pragma unroll
    for (int mt = 0; mt < 2; mt++) {
        int q = wm + (mt << 4) + g;
#pragma unroll
        for (int nt = 0; nt < 8; nt++) {
            int p = (nt << 3) + (tg << 1);
            {
                int t = tb + q;
                float2 xv = __half22float2(*(const __half2*)(xbc + (size_t)t * CONVD + h * 64 + p));
                *(__half2*)(y + (size_t)t * Ee + h * 64 + p) =
                    __floats2half2_rn(acc[mt][nt][0] + Dh * xv.x, acc[mt][nt][1] + Dh * xv.y);
            }
            {
                int t = tb + q + 8;
                float2 xv = __half22float2(*(const __half2*)(xbc + (size_t)t * CONVD + h * 64 + p));
                *(__half2*)(y + (size_t)t * Ee + h * 64 + p) =
                    __floats2half2_rn(acc[mt][nt][2] + Dh * xv.x, acc[mt][nt][3] + Dh * xv.y);
            }
        }
    }
}

// ---------------- inter-chunk recurrence (4x column split) ----------------
__global__ void chunk_scan_kernel(const float* __restrict__ states,
                                  const float* __restrict__ acs,
                                  float* __restrict__ prefix) {
    int b = blockIdx.x, h = blockIdx.y, seg = blockIdx.z;
    int tid = threadIdx.x;
    int base_e = seg * 2048;
    float run[8];
#pragma unroll
    for (int i = 0; i < 8; i++) run[i] = 0.f;
    for (int ch = 0; ch < 16; ch++) {
        int bc = b * 16 + ch;
        size_t base = (size_t)(bc * NHh + h) * 8192 + base_e;
        float al = expf(acs[(bc * NHh + h) * Qq + 127]);
#pragma unroll
        for (int i = 0; i < 8; i++) {
            int e = (i << 8) + tid;
            prefix[base + e] = run[i];
            run[i] = run[i] * al + states[base + e];
        }
    }
}

// ---------------- CB (split over q; half input) ----------------
__global__ __launch_bounds__(256) void cb_kernel(const __half* __restrict__ xbc,
                                                 float* __restrict__ cbout) {
    int bc = blockIdx.x;
    int q0 = blockIdx.y << 6;
    int tb = ((bc >> 4) << 11) + ((bc & 15) << 7);
    __shared__ float Ct[64][33];
    __shared__ float Bt[128][33];
    int tid = threadIdx.x;
    int tq = tid >> 4, ts = tid & 15;
    float acc[4][8] = {};
    for (int nt = 0; nt < 128; nt += 32) {
        for (int i = tid; i < 2048; i += 256) {
            int r = i >> 5, nn = i & 31;
            Ct[r][nn] = __half2float(xbc[(size_t)(tb + q0 + r) * CONVD + 2176 + nt + nn]);
        }
        for (int i = tid; i < 4096; i += 256) {
            int r = i >> 5, nn = i & 31;
            Bt[r][nn] = __half2float(xbc[(size_t)(tb + r) * CONVD + 2048 + nt + nn]);
        }
        __syncthreads();
        for (int nn = 0; nn < 32; nn++) {
            float ca[4], bb[8];
#pragma unroll
            for (int i = 0; i < 4; i++) ca[i] = Ct[tq * 4 + i][nn];
#pragma unroll
            for (int j = 0; j < 8; j++) bb[j] = Bt[ts * 8 + j][nn];
#pragma unroll
            for (int i = 0; i < 4; i++)
#pragma unroll
                for (int j = 0; j < 8; j++) acc[i][j] += ca[i] * bb[j];
        }
        __syncthreads();
    }
    float* o = cbout + (size_t)bc * 16384;
#pragma unroll
    for (int i = 0; i < 4; i++)
#pragma unroll
        for (int j = 0; j < 8; j++)
            o[(q0 + tq * 4 + i) * 128 + ts * 8 + j] = acc[i][j];
}

// ---------------- host launcher ----------------
extern "C" void kernel_launch(void* const* d_in, const int* in_sizes, int n_in,
                              void* d_out, int out_size) {
    const float* hid   = (const float*)d_in[0];
    const float* wln1  = (const float*)d_in[1];
    const float* win   = (const float*)d_in[2];
    const float* wconv = (const float*)d_in[3];
    const float* bcv   = (const float*)d_in[4];
    const float* dtb   = (const float*)d_in[5];
    const float* alog  = (const float*)d_in[6];
    const float* Dw    = (const float*)d_in[7];
    const float* wmn   = (const float*)d_in[8];
    const float* wout  = (const float*)d_in[9];
    const float* wln2  = (const float*)d_in[10];
    const float* wg    = (const float*)d_in[11];
    const float* wu    = (const float*)d_in[12];
    const float* wd    = (const float*)d_in[13];
    float* out = (float*)d_out;

    __half *hnorm, *zh, *xbch, *yh, *y2, *h2n, *ggh, *gu, *wh_in, *wh_out, *wh_g, *wh_u, *wh_d;
    float *zx, *dt, *acs, *states, *prefix, *cbp, *hid2;
    cudaGetSymbolAddress((void**)&hnorm,  g_hnorm);
    cudaGetSymbolAddress((void**)&zx,     g_zx);
    cudaGetSymbolAddress((void**)&zh,     g_zh);
    cudaGetSymbolAddress((void**)&xbch,   g_xbch);
    cudaGetSymbolAddress((void**)&dt,     g_dt);
    cudaGetSymbolAddress((void**)&acs,    g_acs);
    cudaGetSymbolAddress((void**)&states, g_states);
    cudaGetSymbolAddress((void**)&prefix, g_prefix);
    cudaGetSymbolAddress((void**)&cbp,    g_cb);
    cudaGetSymbolAddress((void**)&yh,     g_yh);
    cudaGetSymbolAddress((void**)&y2,     g_y2);
    cudaGetSymbolAddress((void**)&hid2,   g_hid2);
    cudaGetSymbolAddress((void**)&h2n,    g_h2n);
    cudaGetSymbolAddress((void**)&ggh,    g_gateh);
    cudaGetSymbolAddress((void**)&gu,     g_gu);
    cudaGetSymbolAddress((void**)&wh_in,  g_wh_in);
    cudaGetSymbolAddress((void**)&wh_out, g_wh_out);
    cudaGetSymbolAddress((void**)&wh_g,   g_wh_g);
    cudaGetSymbolAddress((void**)&wh_u,   g_wh_u);
    cudaGetSymbolAddress((void**)&wh_d,   g_wh_d);

    cudaFuncSetAttribute(mma_gemm<0>, cudaFuncAttributeMaxDynamicSharedMemorySize, GEMM_DSMEM);
    cudaFuncSetAttribute(mma_gemm<1>, cudaFuncAttributeMaxDynamicSharedMemorySize, GEMM_DSMEM);
    cudaFuncSetAttribute(mma_gemm<2>, cudaFuncAttributeMaxDynamicSharedMemorySize, GEMM_DSMEM);
    cudaFuncSetAttribute(mma_gemm<3>, cudaFuncAttributeMaxDynamicSharedMemorySize, GEMM_DSMEM);
    cudaFuncSetAttribute(chunk_states_mma, cudaFuncAttributeMaxDynamicSharedMemorySize, CS_DSMEM);
    cudaFuncSetAttribute(y_mma_kernel, cudaFuncAttributeMaxDynamicSharedMemorySize, Y_DSMEM);

    // 0) in-proj weights -> fp16
    round_h4_kernel<<<(DIN * Hh / 4 + 255) / 256, 256>>>((const float4*)win, (uint2*)wh_in, DIN * Hh / 4);
    // 1) pre-norm
    rmsnorm_kernel<<<TOK, 256>>>(hid, wln1, hnorm, Hh, EPS1);
    // 2) in-projection (split store: z half -> zh, rest fp32 -> zx)
    mma_gemm<0><<<dim3((DIN + 127) / 128, TOK / 128), 256, GEMM_DSMEM>>>(hnorm, wh_in, nullptr, zx, zh, TOK, DIN, Hh, 0);
    // 3) conv + silu (4 timesteps/thread)
    conv_silu4t_kernel<<<((TOK / 4) * CONVD + 255) / 256, 256>>>(zx, (const float4*)wconv, bcv, xbch);
    // 4) dt + cumsum
    dtdacs_kernel<<<dim3(NCHUNK, NHh), 128>>>(zx, dtb, alog, dt, acs);
    // 5) chunk states (mma)
    chunk_states_mma<<<dim3(NCHUNK, NHh), 128, CS_DSMEM>>>(xbch, dt, acs, states);
    // 6) scan (4x column split)
    chunk_scan_kernel<<<dim3(2, NHh, 4), 256>>>(states, acs, prefix);
    // 7) CB
    cb_kernel<<<dim3(NCHUNK, 2), 256>>>(xbch, cbp);
    // 8) Y (mma)
    y_mma_kernel<<<dim3(NCHUNK, NHh), 128, Y_DSMEM>>>(xbch, dt, acs, prefix, cbp, Dw, yh);
    // 9) remaining weights -> fp16
    {
        int ntot = (Hh * Ee + FFd * Hh + FFd * Hh + Hh * FFd) / 4;
        round4v_kernel<<<(ntot + 255) / 256, 256>>>(
            (const float4*)wout, (uint2*)wh_out, Hh * Ee / 4,
            (const float4*)wg,   (uint2*)wh_g,   FFd * Hh / 4,
            (const float4*)wu,   (uint2*)wh_u,   FFd * Hh / 4,
            (const float4*)wd,   (uint2*)wh_d,   Hh * FFd / 4);
    }
    // 10) gated norm (half z)
    gated_rmsnorm_kernel<<<TOK, 256>>>(yh, zh, wmn, y2);
    // 11) out-proj + residual
    mma_gemm<1><<<dim3(Hh / 128, TOK / 128), 256, GEMM_DSMEM>>>(y2, wh_out, hid, hid2, nullptr, TOK, Hh, Ee, 0);
    // 12) norm 2
    rmsnorm_kernel<<<TOK, 256>>>(hid2, wln2, h2n, Hh, EPS1);
    // 13) gate projection (half out)
    mma_gemm<3><<<dim3(FFd / 128, TOK / 128), 256, GEMM_DSMEM>>>(h2n, wh_g, nullptr, nullptr, ggh, TOK, FFd, Hh, 0);
    // 14) up projection + fused silu(gate)*up
    mma_gemm<2><<<dim3(FFd / 128, TOK / 128), 256, GEMM_DSMEM>>>(h2n, wh_u, ggh, nullptr, gu, TOK, FFd, Hh, 0);
    // 15) down + residual -> output
    mma_gemm<1><<<dim3(Hh / 128, TOK / 128), 256, GEMM_DSMEM>>>(gu, wh_d, hid2, out, nullptr, TOK, Hh, FFd, 0);
}

// round 17
// speedup vs baseline: 1.2326x; 1.0225x over previous
#include <cuda_runtime.h>
#include <cuda_fp16.h>
#include <cstdint>
#include <math.h>

// ---------------- problem dims ----------------
#define TOK   4096
#define SEQL  2048
#define Hh    1024
#define Ee    2048
#define NHh   32
#define Nn    128
#define Qq    128
#define Kc    4
#define CONVD 2304
#define DIN   4384
#define FFd   4096
#define NCHUNK 32
#define EPS1  1e-6f
#define NEPS  1e-5f

// ---------------- scratch ----------------
__device__ __half g_hnorm [TOK * Hh];
__device__ float  g_zx    [TOK * DIN];
__device__ __half g_zh    [TOK * Ee];
__device__ __half g_xbch  [TOK * CONVD];
__device__ float  g_dt    [TOK * NHh];
__device__ float  g_acs   [NCHUNK * NHh * Qq];
__device__ __half g_states[NCHUNK * NHh * 64 * Nn];
__device__ __half g_prefix[NCHUNK * NHh * 64 * Nn];
__device__ float  g_cb    [NCHUNK * Qq * Qq];
__device__ __half g_yh    [TOK * Ee];
__device__ __half g_y2    [TOK * Ee];
__device__ float  g_hid2  [TOK * Hh];
__device__ __half g_h2n   [TOK * Hh];
__device__ __half g_gateh [TOK * FFd];
__device__ __half g_gu    [TOK * FFd];
// fp16 weights
__device__ __half g_wh_in [DIN * Hh];
__device__ __half g_wh_out[Hh * Ee];
__device__ __half g_wh_g  [FFd * Hh];
__device__ __half g_wh_u  [FFd * Hh];
__device__ __half g_wh_d  [Hh * FFd];

// ---------------- helpers ----------------
__device__ __forceinline__ uint32_t smem_u32(const void* p) {
    return (uint32_t)__cvta_generic_to_shared(p);
}
__device__ __forceinline__ float silu_f(float x) { return x / (1.f + expf(-x)); }
__device__ __forceinline__ float block_sum_256(float v) {
    __shared__ float sh[8];
    __syncthreads();
    int lane = threadIdx.x & 31, wid = threadIdx.x >> 5;
#pragma unroll
    for (int o = 16; o > 0; o >>= 1) v += __shfl_down_sync(0xffffffffu, v, o);
    if (lane == 0) sh[wid] = v;
    __syncthreads();
    if (threadIdx.x == 0) {
        float s = 0.f;
#pragma unroll
        for (int i = 0; i < 8; i++) s += sh[i];
        sh[0] = s;
    }
    __syncthreads();
    return sh[0];
}
__device__ __forceinline__ void cp_async16(uint32_t dst, const void* src, int sz) {
    asm volatile("cp.async.cg.shared.global [%0], [%1], 16, %2;"
                 :: "r"(dst), "l"((unsigned long long)__cvta_generic_to_global(src)), "r"(sz)
                 : "memory");
}
__device__ __forceinline__ void ldsm_x4(uint32_t& r0, uint32_t& r1, uint32_t& r2, uint32_t& r3,
                                        uint32_t addr) {
    asm volatile("ldmatrix.sync.aligned.m8n8.x4.shared.b16 {%0,%1,%2,%3}, [%4];"
                 : "=r"(r0), "=r"(r1), "=r"(r2), "=r"(r3) : "r"(addr));
}
__device__ __forceinline__ uint2 f4_to_h4(float4 v) {
    __half2 lo = __floats2half2_rn(v.x, v.y);
    __half2 hi = __floats2half2_rn(v.z, v.w);
    return make_uint2(*(uint32_t*)&lo, *(uint32_t*)&hi);
}
__device__ __forceinline__ void mma_16816(float* a4, const uint32_t* fa, uint32_t b0, uint32_t b1) {
    asm volatile(
        "mma.sync.aligned.m16n8k16.row.col.f32.f16.f16.f32 "
        "{%0,%1,%2,%3}, {%4,%5,%6,%7}, {%8,%9}, {%0,%1,%2,%3};"
        : "+f"(a4[0]), "+f"(a4[1]), "+f"(a4[2]), "+f"(a4[3])
        : "r"(fa[0]), "r"(fa[1]), "r"(fa[2]), "r"(fa[3]), "r"(b0), "r"(b1));
}

// ---------------- fp16 mma.sync GEMM (128x128, 5-stage, 2 CTA/SM) ----------------
#define GSTAGES 5
#define LDSTH 40
#define STAGE_HALVES (256 * LDSTH)
#define STAGE_BYTES  (STAGE_HALVES * 2)
#define GEMM_DSMEM (GSTAGES * STAGE_BYTES)

template<int MODE>
__global__ __launch_bounds__(256, 2) void mma_gemm(
    const __half* __restrict__ A, const __half* __restrict__ B,
    const void* __restrict__ aux, float* __restrict__ Cf, __half* __restrict__ Ch,
    int M, int N, int K, int col_base)
{
    extern __shared__ __half smh[];
    int tid = threadIdx.x;
    int lane = tid & 31, wid = tid >> 5;
    int g = lane >> 2, tg = lane & 3;
    int wm = (wid >> 1) << 5;
    int wn = (wid & 1) << 6;
    int row0 = blockIdx.y << 7, col0 = (blockIdx.x << 7) + col_base;
    int NC = K >> 5;
    uint32_t smbase = smem_u32(smh);

    uint32_t aoff[2], boff[4];
#pragma unroll
    for (int mt = 0; mt < 2; mt++)
        aoff[mt] = ((wm + (mt << 4) + (lane & 15)) * LDSTH + ((lane >> 4) << 3)) * 2;
#pragma unroll
    for (int ntp = 0; ntp < 4; ntp++)
        boff[ntp] = (128 * LDSTH + (wn + (ntp << 4) + (lane & 7) + (((lane >> 4) & 1) << 3)) * LDSTH
                     + (((lane >> 3) & 1) << 3)) * 2;

    float acc[2][8][4];
#pragma unroll
    for (int i = 0; i < 2; i++)
#pragma unroll
        for (int j = 0; j < 8; j++)
#pragma unroll
            for (int k = 0; k < 4; k++) acc[i][j][k] = 0.f;

    auto load_stage = [&](int s, int c) {
        __half* As = smh + s * STAGE_HALVES;
        __half* Bs = As + 128 * LDSTH;
        const __half* Ag = A + (size_t)row0 * K + (c << 5);
        const __half* Bg = B + (size_t)col0 * K + (c << 5);
#pragma unroll
        for (int it = 0; it < 4; it++) {
            int i = tid + (it << 8);
            if (i < 512) {
                int r = i >> 2, c8 = (i & 3) << 3;
                cp_async16(smem_u32(As + r * LDSTH + c8), Ag + (size_t)r * K + c8, 16);
            } else {
                int j = i - 512;
                int r = j >> 2, c8 = (j & 3) << 3;
                int sz = (col0 + r < N) ? 16 : 0;
                cp_async16(smem_u32(Bs + r * LDSTH + c8), Bg + (size_t)r * K + c8, sz);
            }
        }
    };

    uint32_t fa0[2][4], fb0[4][4], fa1[2][4], fb1[4][4];

    auto load_frags = [&](uint32_t (&fa)[2][4], uint32_t (&fb)[4][4], uint32_t stb, int ks) {
        uint32_t kb = stb + (ks << 5);
#pragma unroll
        for (int mt = 0; mt < 2; mt++)
            ldsm_x4(fa[mt][0], fa[mt][1], fa[mt][2], fa[mt][3], kb + aoff[mt]);
#pragma unroll
        for (int ntp = 0; ntp < 4; ntp++)
            ldsm_x4(fb[ntp][0], fb[ntp][1], fb[ntp][2], fb[ntp][3], kb + boff[ntp]);
    };
    auto do_mma = [&](uint32_t (&fa)[2][4], uint32_t (&fb)[4][4]) {
#pragma unroll
        for (int mt = 0; mt < 2; mt++)
#pragma unroll
            for (int nt = 0; nt < 8; nt++)
                mma_16816(acc[mt][nt], fa[mt],
                          fb[nt >> 1][((nt & 1) << 1)], fb[nt >> 1][((nt & 1) << 1) + 1]);
    };

#pragma unroll
    for (int s = 0; s < GSTAGES - 1; s++) {
        load_stage(s, s);
        asm volatile("cp.async.commit_group;" ::: "memory");
    }
    asm volatile("cp.async.wait_group %0;" :: "n"(GSTAGES - 2) : "memory");
    __syncthreads();
    load_frags(fa0, fb0, smbase, 0);

    for (int c = 0; c < NC; c++) {
        int nxt = c + GSTAGES - 1;
        if (nxt < NC) load_stage(nxt % GSTAGES, nxt);
        asm volatile("cp.async.commit_group;" ::: "memory");

        uint32_t stb = smbase + (c % GSTAGES) * STAGE_BYTES;
        load_frags(fa1, fb1, stb, 1);
        do_mma(fa0, fb0);

        if (c + 1 < NC) {
            asm volatile("cp.async.wait_group %0;" :: "n"(GSTAGES - 2) : "memory");
            __syncthreads();
            load_frags(fa0, fb0, smbase + ((c + 1) % GSTAGES) * STAGE_BYTES, 0);
        }
        do_mma(fa1, fb1);
    }

    // epilogue
#pragma unroll
    for (int mt = 0; mt < 2; mt++) {
        int r = row0 + wm + (mt << 4) + g;
#pragma unroll
        for (int nt = 0; nt < 8; nt++) {
            int cc = col0 + wn + (nt << 3) + (tg << 1);
            if (cc >= N) continue;
            float v0 = acc[mt][nt][0], v1 = acc[mt][nt][1];
            float v2 = acc[mt][nt][2], v3 = acc[mt][nt][3];
            if (MODE == 0) {
                if (cc < Ee) {
                    *(__half2*)(Ch + (size_t)r * Ee + cc) = __floats2half2_rn(v0, v1);
                    *(__half2*)(Ch + (size_t)(r + 8) * Ee + cc) = __floats2half2_rn(v2, v3);
                } else {
                    *(float2*)(Cf + (size_t)r * N + cc) = make_float2(v0, v1);
                    *(float2*)(Cf + (size_t)(r + 8) * N + cc) = make_float2(v2, v3);
                }
            } else if (MODE == 1) {
                const float* af = (const float*)aux;
                float2 s0 = *(const float2*)(af + (size_t)r * N + cc);
                float2 s1 = *(const float2*)(af + (size_t)(r + 8) * N + cc);
                *(float2*)(Cf + (size_t)r * N + cc) = make_float2(v0 + s0.x, v1 + s0.y);
                *(float2*)(Cf + (size_t)(r + 8) * N + cc) = make_float2(v2 + s1.x, v3 + s1.y);
            } else if (MODE == 2) {
                const __half* ah = (const __half*)aux;
                float2 gf0 = __half22float2(*(const __half2*)(ah + (size_t)r * N + cc));
                float2 gf1 = __half22float2(*(const __half2*)(ah + (size_t)(r + 8) * N + cc));
                *(__half2*)(Ch + (size_t)r * N + cc) =
                    __floats2half2_rn(silu_f(gf0.x) * v0, silu_f(gf0.y) * v1);
                *(__half2*)(Ch + (size_t)(r + 8) * N + cc) =
                    __floats2half2_rn(silu_f(gf1.x) * v2, silu_f(gf1.y) * v3);
            } else {
                *(__half2*)(Ch + (size_t)r * N + cc) = __floats2half2_rn(v0, v1);
                *(__half2*)(Ch + (size_t)(r + 8) * N + cc) = __floats2half2_rn(v2, v3);
            }
        }
    }
}

// ---------------- weight fp16 conversions ----------------
__global__ void round_h4_kernel(const float4* __restrict__ in, uint2* __restrict__ out, int n4) {
    int i = blockIdx.x * blockDim.x + threadIdx.x;
    if (i < n4) out[i] = f4_to_h4(in[i]);
}
__global__ void round4v_kernel(const float4* __restrict__ s0, uint2* __restrict__ d0, int n0,
                               const float4* __restrict__ s1, uint2* __restrict__ d1, int n1,
                               const float4* __restrict__ s2, uint2* __restrict__ d2, int n2,
                               const float4* __restrict__ s3, uint2* __restrict__ d3, int n3) {
    int i = blockIdx.x * blockDim.x + threadIdx.x;
    if (i < n0) { d0[i] = f4_to_h4(s0[i]); return; }
    i -= n0;
    if (i < n1) { d1[i] = f4_to_h4(s1[i]); return; }
    i -= n1;
    if (i < n2) { d2[i] = f4_to_h4(s2[i]); return; }
    i -= n2;
    if (i < n3) d3[i] = f4_to_h4(s3[i]);
}

// ---------------- rmsnorm (half output) ----------------
__global__ void rmsnorm_kernel(const float* __restrict__ x, const float* __restrict__ w,
                               __half* __restrict__ out, int cols, float eps) {
    int row = blockIdx.x;
    const float* xr = x + (size_t)row * cols;
    __half* orow = out + (size_t)row * cols;
    int per = cols >> 8;
    float xv[8];
    float ss = 0.f;
    for (int i = 0; i < per; i++) {
        float v = xr[threadIdx.x + (i << 8)];
        xv[i] = v; ss += v * v;
    }
    float tot = block_sum_256(ss);
    float scale = rsqrtf(tot / (float)cols + eps);
    for (int i = 0; i < per; i++) {
        int c = threadIdx.x + (i << 8);
        orow[c] = __float2half(xv[i] * scale * w[c]);
    }
}

// gated rmsnorm: y fp16, z fp16 (stride Ee)
__global__ void gated_rmsnorm_kernel(const __half* __restrict__ y, const __half* __restrict__ zh,
                                     const float* __restrict__ w, __half* __restrict__ out) {
    int row = blockIdx.x;
    const __half* yr = y + (size_t)row * Ee;
    const __half* zr = zh + (size_t)row * Ee;
    __half* orow = out + (size_t)row * Ee;
    float g[8];
    float ss = 0.f;
#pragma unroll
    for (int i = 0; i < 8; i++) {
        int c = threadIdx.x + (i << 8);
        float v = __half2float(yr[c]) * silu_f(__half2float(zr[c]));
        g[i] = v; ss += v * v;
    }
    float tot = block_sum_256(ss);
    float scale = rsqrtf(tot / (float)Ee + NEPS);
#pragma unroll
    for (int i = 0; i < 8; i++) {
        int c = threadIdx.x + (i << 8);
        orow[c] = __float2half(g[i] * scale * w[c]);
    }
}

// ---------------- conv + silu: 4 timesteps/thread ----------------
__global__ void conv_silu4t_kernel(const float* __restrict__ zx,
                                   const float4* __restrict__ wc4,
                                   const float* __restrict__ bcv,
                                   __half* __restrict__ xbc) {
    int idx = blockIdx.x * blockDim.x + threadIdx.x;
    if (idx >= (TOK / 4) * CONVD) return;
    int tq = idx / CONVD, c = idx - tq * CONVD;
    int t0 = tq << 2;
    int pos0 = t0 & (SEQL - 1);
    float4 w = wc4[c];
    float b = bcv[c];
    float z[7];
#pragma unroll
    for (int j = 0; j < 3; j++)
        z[j] = (pos0 + j - 3 >= 0) ? zx[(size_t)(t0 + j - 3) * DIN + Ee + c] : 0.f;
#pragma unroll
    for (int j = 3; j < 7; j++)
        z[j] = zx[(size_t)(t0 + j - 3) * DIN + Ee + c];
#pragma unroll
    for (int i = 0; i < 4; i++) {
        float s = b + w.x * z[i] + w.y * z[i + 1] + w.z * z[i + 2] + w.w * z[i + 3];
        xbc[(size_t)(t0 + i) * CONVD + c] = __float2half(silu_f(s));
    }
}

// ---------------- dt softplus + per-chunk cumsum ----------------
__global__ void dtdacs_kernel(const float* __restrict__ zx, const float* __restrict__ dtb,
                              const float* __restrict__ alog,
                              float* __restrict__ dt, float* __restrict__ acs) {
    int bc = blockIdx.x, h = blockIdx.y;
    int tb = ((bc >> 4) << 11) + ((bc & 15) << 7);
    int q = threadIdx.x;
    int t = tb + q;
    float x = zx[(size_t)t * DIN + (Ee + CONVD) + h] + dtb[h];
    float d = (x > 20.f) ? x : log1pf(expf(x));
    dt[t * NHh + h] = d;
    float a = -expf(alog[h]);
    float v = d * a;
    int lane = q & 31;
#pragma unroll
    for (int o = 1; o < 32; o <<= 1) {
        float n = __shfl_up_sync(0xffffffffu, v, o);
        if (lane >= o) v += n;
    }
    __shared__ float ws[4];
    int wid = q >> 5;
    if (lane == 31) ws[wid] = v;
    __syncthreads();
    float add = 0.f;
    for (int w = 0; w < wid; w++) add += ws[w];
    acs[(bc * NHh + h) * Qq + q] = v + add;
}

// ================= SSD on tensor cores =================
#define SST 136

#define CS_DSMEM (192 * SST * 2 + 512)
__global__ __launch_bounds__(128) void chunk_states_mma(
    const __half* __restrict__ xbc, const float* __restrict__ dt,
    const float* __restrict__ acs, __half* __restrict__ states) {
    extern __shared__ __half smh[];
    __half* Ah = smh;
    __half* Bh = smh + 64 * SST;
    float* wsh = (float*)(smh + 192 * SST);

    int bc = blockIdx.x, h = blockIdx.y;
    int tb = ((bc >> 4) << 11) + ((bc & 15) << 7);
    int tid = threadIdx.x, lane = tid & 31, wid = tid >> 5;
    int g = lane >> 2, tg = lane & 3;

    const float* ac = acs + (bc * NHh + h) * Qq;
    if (tid < 128) {
        float last = ac[127];
        wsh[tid] = __expf(last - ac[tid]) * dt[(tb + tid) * NHh + h];
    }
    __syncthreads();

    for (int i = tid; i < 64 * 128; i += 128) {
        int q = i >> 6, p = i & 63;
        float v = __half2float(xbc[(size_t)(tb + q) * CONVD + h * 64 + p]) * wsh[q];
        Ah[p * SST + q] = __float2half(v);
    }
    for (int i = tid; i < 128 * 128; i += 128) {
        int q = i >> 7, n = i & 127;
        Bh[n * SST + q] = xbc[(size_t)(tb + q) * CONVD + 2048 + n];
    }
    __syncthreads();

    int wm = (wid >> 1) << 5;
    int wn = (wid & 1) << 6;
    uint32_t abase = smem_u32(Ah), bbase = smem_u32(Bh);
    uint32_t aoff[2], boff[4];
#pragma unroll
    for (int mt = 0; mt < 2; mt++)
        aoff[mt] = abase + ((wm + (mt << 4) + (lane & 15)) * SST + ((lane >> 4) << 3)) * 2;
#pragma unroll
    for (int ntp = 0; ntp < 4; ntp++)
        boff[ntp] = bbase + ((wn + (ntp << 4) + (lane & 7) + (((lane >> 4) & 1) << 3)) * SST
                             + (((lane >> 3) & 1) << 3)) * 2;

    float acc[2][8][4] = {};
#pragma unroll
    for (int ks = 0; ks < 8; ks++) {
        uint32_t kb = ks << 5;
        uint32_t fa[2][4], fb[4][4];
#pragma unroll
        for (int mt = 0; mt < 2; mt++)
            ldsm_x4(fa[mt][0], fa[mt][1], fa[mt][2], fa[mt][3], aoff[mt] + kb);
#pragma unroll
        for (int ntp = 0; ntp < 4; ntp++)
            ldsm_x4(fb[ntp][0], fb[ntp][1], fb[ntp][2], fb[ntp][3], boff[ntp] + kb);
#pragma unroll
        for (int mt = 0; mt < 2; mt++)
#pragma unroll
            for (int nt = 0; nt < 8; nt++)
                mma_16816(acc[mt][nt], fa[mt],
                          fb[nt >> 1][((nt & 1) << 1)], fb[nt >> 1][((nt & 1) << 1) + 1]);
    }

    __half* sp = states + (size_t)(bc * NHh + h) * 8192;
#pragma unroll
    for (int mt = 0; mt < 2; mt++) {
        int p = wm + (mt << 4) + g;
#pragma unroll
        for (int nt = 0; nt < 8; nt++) {
            int n = wn + (nt << 3) + (tg << 1);
            *(__half2*)(sp + p * 128 + n) = __floats2half2_rn(acc[mt][nt][0], acc[mt][nt][1]);
            *(__half2*)(sp + (p + 8) * 128 + n) = __floats2half2_rn(acc[mt][nt][2], acc[mt][nt][3]);
        }
    }
}

#define Y_DSMEM (192 * SST * 2 + 3 * 128 * 4)
__global__ __launch_bounds__(128) void y_mma_kernel(
    const __half* __restrict__ xbc, const float* __restrict__ dt,
    const float* __restrict__ acs, const __half* __restrict__ prefix,
    const float* __restrict__ cb, const float* __restrict__ Dw,
    __half* __restrict__ y) {
    extern __shared__ __half smh[];
    __half* Ah = smh;
    __half* Bh = smh + 128 * SST;
    float* acs_s = (float*)(smh + 192 * SST);
    float* dts   = acs_s + 128;
    float* eqs   = dts + 128;

    int bc = blockIdx.x, h = blockIdx.y;
    int tb = ((bc >> 4) << 11) + ((bc & 15) << 7);
    int tid = threadIdx.x, lane = tid & 31, wid = tid >> 5;
    int g = lane >> 2, tg = lane & 3;

    if (tid < 128) {
        float a = acs[(bc * NHh + h) * Qq + tid];
        acs_s[tid] = a;
        eqs[tid] = __expf(a);
        dts[tid] = dt[(tb + tid) * NHh + h];
    }
    __syncthreads();

    const float* cbb = cb + (size_t)bc * 16384;
    for (int i = tid; i < 128 * 128; i += 128) {
        int q = i >> 7, s = i & 127;
        float v = (s <= q) ? cbb[q * 128 + s] * __expf(acs_s[q] - acs_s[s]) : 0.f;
        Ah[q * SST + s] = __float2half(v);
    }
    for (int i = tid; i < 64 * 128; i += 128) {
        int s = i >> 6, p = i & 63;
        float xv = __half2float(xbc[(size_t)(tb + s) * CONVD + h * 64 + p]);
        Bh[p * SST + s] = __float2half(xv * dts[s]);
    }
    __syncthreads();

    int wm = wid << 5;
    uint32_t abase = smem_u32(Ah), bbase = smem_u32(Bh);
    uint32_t aoff[2], boff[4];
#pragma unroll
    for (int mt = 0; mt < 2; mt++)
        aoff[mt] = abase + ((wm + (mt << 4) + (lane & 15)) * SST + ((lane >> 4) << 3)) * 2;
#pragma unroll
    for (int ntp = 0; ntp < 4; ntp++)
        boff[ntp] = bbase + (((ntp << 4) + (lane & 7) + (((lane >> 4) & 1) << 3)) * SST
                             + (((lane >> 3) & 1) << 3)) * 2;

    float acc[2][8][4] = {};
    auto run_phase = [&]() {
#pragma unroll
        for (int ks = 0; ks < 8; ks++) {
            uint32_t kb = ks << 5;
            uint32_t fa[2][4], fb[4][4];
#pragma unroll
            for (int mt = 0; mt < 2; mt++)
                ldsm_x4(fa[mt][0], fa[mt][1], fa[mt][2], fa[mt][3], aoff[mt] + kb);
#pragma unroll
            for (int ntp = 0; ntp < 4; ntp++)
                ldsm_x4(fb[ntp][0], fb[ntp][1], fb[ntp][2], fb[ntp][3], boff[ntp] + kb);
#pragma unroll
            for (int mt = 0; mt < 2; mt++)
#pragma unroll
                for (int nt = 0; nt < 8; nt++)
                    mma_16816(acc[mt][nt], fa[mt],
                              fb[nt >> 1][((nt & 1) << 1)], fb[nt >> 1][((nt & 1) << 1) + 1]);
        }
    };
    run_phase();
    __syncthreads();

    for (int i = tid; i < 128 * 128; i += 128) {
        int q = i >> 7, n = i & 127;
        float cv = __half2float(xbc[(size_t)(tb + q) * CONVD + 2176 + n]);
        Ah[q * SST + n] = __float2half(cv * eqs[q]);
    }
    const __half* pref = prefix + (size_t)(bc * NHh + h) * 8192;
    for (int i = tid; i < 64 * 128; i += 128) {
        int p = i >> 7, n = i & 127;
        Bh[p * SST + n] = pref[p * 128 + n];
    }
    __syncthreads();
    run_phase();

    float Dh = Dw[h];
#pragma unroll
    for (int mt = 0; mt < 2; mt++) {
        int q = wm + (mt << 4) + g;
#pragma unroll
        for (int nt = 0; nt < 8; nt++) {
            int p = (nt << 3) + (tg << 1);
            {
                int t = tb + q;
                float2 xv = __half22float2(*(const __half2*)(xbc + (size_t)t * CONVD + h * 64 + p));
                *(__half2*)(y + (size_t)t * Ee + h * 64 + p) =
                    __floats2half2_rn(acc[mt][nt][0] + Dh * xv.x, acc[mt][nt][1] + Dh * xv.y);
            }
            {
                int t = tb + q + 8;
                float2 xv = __half22float2(*(const __half2*)(xbc + (size_t)t * CONVD + h * 64 + p));
                *(__half2*)(y + (size_t)t * Ee + h * 64 + p) =
                    __floats2half2_rn(acc[mt][nt][2] + Dh * xv.x, acc[mt][nt][3] + Dh * xv.y);
            }
        }
    }
}

// ---------------- inter-chunk recurrence (fp16 storage, fp32 accumulate) ----------------
__global__ void chunk_scan_kernel(const __half* __restrict__ states,
                                  const float* __restrict__ acs,
                                  __half* __restrict__ prefix) {
    int b = blockIdx.x, h = blockIdx.y, seg = blockIdx.z;
    int tid = threadIdx.x;
    int base_e = seg * 2048;
    float run[8];
#pragma unroll
    for (int i = 0; i < 8; i++) run[i] = 0.f;
    for (int ch = 0; ch < 16; ch++) {
        int bc = b * 16 + ch;
        size_t base = (size_t)(bc * NHh + h) * 8192 + base_e;
        float al = expf(acs[(bc * NHh + h) * Qq + 127]);
#pragma unroll
        for (int i = 0; i < 8; i++) {
            int e = (i << 8) + tid;
            prefix[base + e] = __float2half(run[i]);
            run[i] = run[i] * al + __half2float(states[base + e]);
        }
    }
}

// ---------------- CB (split over q; half input) ----------------
__global__ __launch_bounds__(256) void cb_kernel(const __half* __restrict__ xbc,
                                                 float* __restrict__ cbout) {
    int bc = blockIdx.x;
    int q0 = blockIdx.y << 6;
    int tb = ((bc >> 4) << 11) + ((bc & 15) << 7);
    __shared__ float Ct[64][33];
    __shared__ float Bt[128][33];
    int tid = threadIdx.x;
    int tq = tid >> 4, ts = tid & 15;
    float acc[4][8] = {};
    for (int nt = 0; nt < 128; nt += 32) {
        for (int i = tid; i < 2048; i += 256) {
            int r = i >> 5, nn = i & 31;
            Ct[r][nn] = __half2float(xbc[(size_t)(tb + q0 + r) * CONVD + 2176 + nt + nn]);
        }
        for (int i = tid; i < 4096; i += 256) {
            int r = i >> 5, nn = i & 31;
            Bt[r][nn] = __half2float(xbc[(size_t)(tb + r) * CONVD + 2048 + nt + nn]);
        }
        __syncthreads();
        for (int nn = 0; nn < 32; nn++) {
            float ca[4], bb[8];
#pragma unroll
            for (int i = 0; i < 4; i++) ca[i] = Ct[tq * 4 + i][nn];
#pragma unroll
            for (int j = 0; j < 8; j++) bb[j] = Bt[ts * 8 + j][nn];
#pragma unroll
            for (int i = 0; i < 4; i++)
#pragma unroll
                for (int j = 0; j < 8; j++) acc[i][j] += ca[i] * bb[j];
        }
        __syncthreads();
    }
    float* o = cbout + (size_t)bc * 16384;
#pragma unroll
    for (int i = 0; i < 4; i++)
#pragma unroll
        for (int j = 0; j < 8; j++)
            o[(q0 + tq * 4 + i) * 128 + ts * 8 + j] = acc[i][j];
}

// ---------------- host launcher ----------------
extern "C" void kernel_launch(void* const* d_in, const int* in_sizes, int n_in,
                              void* d_out, int out_size) {
    const float* hid   = (const float*)d_in[0];
    const float* wln1  = (const float*)d_in[1];
    const float* win   = (const float*)d_in[2];
    const float* wconv = (const float*)d_in[3];
    const float* bcv   = (const float*)d_in[4];
    const float* dtb   = (const float*)d_in[5];
    const float* alog  = (const float*)d_in[6];
    const float* Dw    = (const float*)d_in[7];
    const float* wmn   = (const float*)d_in[8];
    const float* wout  = (const float*)d_in[9];
    const float* wln2  = (const float*)d_in[10];
    const float* wg    = (const float*)d_in[11];
    const float* wu    = (const float*)d_in[12];
    const float* wd    = (const float*)d_in[13];
    float* out = (float*)d_out;

    __half *hnorm, *zh, *xbch, *states, *prefix, *yh, *y2, *h2n, *ggh, *gu;
    __half *wh_in, *wh_out, *wh_g, *wh_u, *wh_d;
    float *zx, *dt, *acs, *cbp, *hid2;
    cudaGetSymbolAddress((void**)&hnorm,  g_hnorm);
    cudaGetSymbolAddress((void**)&zx,     g_zx);
    cudaGetSymbolAddress((void**)&zh,     g_zh);
    cudaGetSymbolAddress((void**)&xbch,   g_xbch);
    cudaGetSymbolAddress((void**)&dt,     g_dt);
    cudaGetSymbolAddress((void**)&acs,    g_acs);
    cudaGetSymbolAddress((void**)&states, g_states);
    cudaGetSymbolAddress((void**)&prefix, g_prefix);
    cudaGetSymbolAddress((void**)&cbp,    g_cb);
    cudaGetSymbolAddress((void**)&yh,     g_yh);
    cudaGetSymbolAddress((void**)&y2,     g_y2);
    cudaGetSymbolAddress((void**)&hid2,   g_hid2);
    cudaGetSymbolAddress((void**)&h2n,    g_h2n);
    cudaGetSymbolAddress((void**)&ggh,    g_gateh);
    cudaGetSymbolAddress((void**)&gu,     g_gu);
    cudaGetSymbolAddress((void**)&wh_in,  g_wh_in);
    cudaGetSymbolAddress((void**)&wh_out, g_wh_out);
    cudaGetSymbolAddress((void**)&wh_g,   g_wh_g);
    cudaGetSymbolAddress((void**)&wh_u,   g_wh_u);
    cudaGetSymbolAddress((void**)&wh_d,   g_wh_d);

    cudaFuncSetAttribute(mma_gemm<0>, cudaFuncAttributeMaxDynamicSharedMemorySize, GEMM_DSMEM);
    cudaFuncSetAttribute(mma_gemm<1>, cudaFuncAttributeMaxDynamicSharedMemorySize, GEMM_DSMEM);
    cudaFuncSetAttribute(mma_gemm<2>, cudaFuncAttributeMaxDynamicSharedMemorySize, GEMM_DSMEM);
    cudaFuncSetAttribute(mma_gemm<3>, cudaFuncAttributeMaxDynamicSharedMemorySize, GEMM_DSMEM);
    cudaFuncSetAttribute(chunk_states_mma, cudaFuncAttributeMaxDynamicSharedMemorySize, CS_DSMEM);
    cudaFuncSetAttribute(y_mma_kernel, cudaFuncAttributeMaxDynamicSharedMemorySize, Y_DSMEM);

    // 0) in-proj weights -> fp16
    round_h4_kernel<<<(DIN * Hh / 4 + 255) / 256, 256>>>((const float4*)win, (uint2*)wh_in, DIN * Hh / 4);
    // 1) pre-norm
    rmsnorm_kernel<<<TOK, 256>>>(hid, wln1, hnorm, Hh, EPS1);
    // 2) in-projection (split store: z half -> zh, rest fp32 -> zx)
    mma_gemm<0><<<dim3((DIN + 127) / 128, TOK / 128), 256, GEMM_DSMEM>>>(hnorm, wh_in, nullptr, zx, zh, TOK, DIN, Hh, 0);
    // 3) conv + silu (4 timesteps/thread)
    conv_silu4t_kernel<<<((TOK / 4) * CONVD + 255) / 256, 256>>>(zx, (const float4*)wconv, bcv, xbch);
    // 4) dt + cumsum
    dtdacs_kernel<<<dim3(NCHUNK, NHh), 128>>>(zx, dtb, alog, dt, acs);
    // 5) chunk states (mma, half out)
    chunk_states_mma<<<dim3(NCHUNK, NHh), 128, CS_DSMEM>>>(xbch, dt, acs, states);
    // 6) scan (4x column split, fp16 storage)
    chunk_scan_kernel<<<dim3(2, NHh, 4), 256>>>(states, acs, prefix);
    // 7) CB
    cb_kernel<<<dim3(NCHUNK, 2), 256>>>(xbch, cbp);
    // 8) Y (mma)
    y_mma_kernel<<<dim3(NCHUNK, NHh), 128, Y_DSMEM>>>(xbch, dt, acs, prefix, cbp, Dw, yh);
    // 9) remaining weights -> fp16
    {
        int ntot = (Hh * Ee + FFd * Hh + FFd * Hh + Hh * FFd) / 4;
        round4v_kernel<<<(ntot + 255) / 256, 256>>>(
            (const float4*)wout, (uint2*)wh_out, Hh * Ee / 4,
            (const float4*)wg,   (uint2*)wh_g,   FFd * Hh / 4,
            (const float4*)wu,   (uint2*)wh_u,   FFd * Hh / 4,
            (const float4*)wd,   (uint2*)wh_d,   Hh * FFd / 4);
    }
    // 10) gated norm (half y, half z)
    gated_rmsnorm_kernel<<<TOK, 256>>>(yh, zh, wmn, y2);
    // 11) out-proj + residual
    mma_gemm<1><<<dim3(Hh / 128, TOK / 128), 256, GEMM_DSMEM>>>(y2, wh_out, hid, hid2, nullptr, TOK, Hh, Ee, 0);
    // 12) norm 2
    rmsnorm_kernel<<<TOK, 256>>>(hid2, wln2, h2n, Hh, EPS1);
    // 13) gate projection (half out)
    mma_gemm<3><<<dim3(FFd / 128, TOK / 128), 256, GEMM_DSMEM>>>(h2n, wh_g, nullptr, nullptr, ggh, TOK, FFd, Hh, 0);
    // 14) up projection + fused silu(gate)*up
    mma_gemm<2><<<dim3(FFd / 128, TOK / 128), 256, GEMM_DSMEM>>>(h2n, wh_u, ggh, nullptr, gu, TOK, FFd, Hh, 0);
    // 15) down + residual -> output
    mma_gemm<1><<<dim3(Hh / 128, TOK / 128), 256, GEMM_DSMEM>>>(gu, wh_d, hid2, out, nullptr, TOK, Hh, FFd, 0);
}